// round 2
// baseline (speedup 1.0000x reference)
#include <cuda_runtime.h>
#include <cuda_bf16.h>

// Problem constants
#define Bsz  8
#define Tsz  256
#define Osz  16
#define Dsz  512
#define Hsz  8
#define HDsz 64
#define Mrows (Bsz*Tsz*Osz)      // 32768
#define ELEMS (Mrows*Dsz)        // 16777216

// ---------------------------------------------------------------------------
// Scratch (device globals: no allocation, graph-safe)
// ---------------------------------------------------------------------------
__device__ float g_q[ELEMS];     // layout (b,o,h,t,hd)
__device__ float g_k[ELEMS];     // layout (b,o,h,t,hd)
__device__ float g_v[ELEMS];     // layout (b,o,h,t,hd)
__device__ float g_att[ELEMS];   // layout (b,t,o,d)
__device__ float g_out[ELEMS];   // layout (b,t,o,d)
__device__ float g_mask[Mrows];  // normalized mask (b,t,o) as 0/1 floats

// ---------------------------------------------------------------------------
// Mask normalization: the harness may marshal the jax bool as int32 or as
// 1-byte bools. Detect which (uint32 view containing values >1 => packed
// bytes) and write a canonical float 0/1 array. Single block, deterministic.
// ---------------------------------------------------------------------------
__global__ void mask_norm_k(const void* __restrict__ mraw)
{
    __shared__ int s_bytes;
    const unsigned int*  mi = (const unsigned int*)mraw;
    const unsigned char* mb = (const unsigned char*)mraw;
    if (threadIdx.x == 0) s_bytes = 0;
    __syncthreads();
    for (int i = threadIdx.x; i < Mrows; i += blockDim.x)
        if (mi[i] > 1u) atomicOr(&s_bytes, 1);
    __syncthreads();
    const bool bytes = (s_bytes != 0);
    for (int i = threadIdx.x; i < Mrows; i += blockDim.x)
        g_mask[i] = bytes ? (mb[i] ? 1.f : 0.f) : (mi[i] ? 1.f : 0.f);
}

// ---------------------------------------------------------------------------
// GEMM: C[M=32768, N=512] = X[M,512] @ W[512,512] + bias
// 128x128 block tile, BK=8, 256 threads, 8x8 per-thread microtile.
// MODE 0/1/2: X = organ_states, C = g_q/g_k/g_v written in head-major layout
// MODE 3:     X = g_att,        C = g_out written row-major
// ---------------------------------------------------------------------------
template<int MODE>
__global__ __launch_bounds__(256)
void gemm_k(const float* __restrict__ Xin,
            const float* __restrict__ W,
            const float* __restrict__ bias)
{
    const float* X = (MODE == 3) ? g_att : Xin;
    float* C = (MODE == 0) ? g_q : (MODE == 1) ? g_k : (MODE == 2) ? g_v : g_out;

    __shared__ float As[8][128];
    __shared__ float Bs[8][128];

    const int tid = threadIdx.x;
    const int m0 = blockIdx.y * 128;
    const int n0 = blockIdx.x * 128;
    const int ty = tid >> 4;        // 0..15 (m direction)
    const int tx = tid & 15;        // 0..15 (n direction)

    // global load mapping
    const int arow = tid >> 1;          // 0..127
    const int acol = (tid & 1) * 4;     // 0 or 4
    const int brow = tid >> 5;          // 0..7
    const int bcol = (tid & 31) * 4;    // 0..124

    float acc[8][8];
    #pragma unroll
    for (int i = 0; i < 8; i++)
        #pragma unroll
        for (int j = 0; j < 8; j++)
            acc[i][j] = 0.f;

    const float* xptr = X + (size_t)(m0 + arow) * Dsz + acol;
    const float* wptr = W + (size_t)brow * Dsz + n0 + bcol;

    for (int k0 = 0; k0 < Dsz; k0 += 8) {
        float4 av = *(const float4*)(xptr + k0);
        float4 bv = *(const float4*)(wptr + (size_t)k0 * Dsz);

        __syncthreads();   // protect smem from previous iteration's readers
        As[acol + 0][arow] = av.x;
        As[acol + 1][arow] = av.y;
        As[acol + 2][arow] = av.z;
        As[acol + 3][arow] = av.w;
        *(float4*)&Bs[brow][bcol] = bv;
        __syncthreads();

        #pragma unroll
        for (int kk = 0; kk < 8; kk++) {
            float4 a0 = *(const float4*)&As[kk][ty * 8];
            float4 a1 = *(const float4*)&As[kk][ty * 8 + 4];
            float4 b0 = *(const float4*)&Bs[kk][tx * 8];
            float4 b1 = *(const float4*)&Bs[kk][tx * 8 + 4];
            float a[8] = {a0.x, a0.y, a0.z, a0.w, a1.x, a1.y, a1.z, a1.w};
            float b[8] = {b0.x, b0.y, b0.z, b0.w, b1.x, b1.y, b1.z, b1.w};
            #pragma unroll
            for (int i = 0; i < 8; i++)
                #pragma unroll
                for (int j = 0; j < 8; j++)
                    acc[i][j] = fmaf(a[i], b[j], acc[i][j]);
        }
    }

    // epilogue: bias + layout-specific store
    #pragma unroll
    for (int i = 0; i < 8; i++) {
        int m = m0 + ty * 8 + i;
        int bq  = m >> 12;          // / (T*O) = /4096
        int rem = m & 4095;
        int t = rem >> 4;
        int o = rem & 15;
        #pragma unroll
        for (int j = 0; j < 8; j++) {
            int n = n0 + tx * 8 + j;
            float val = acc[i][j] + bias[n];
            if (MODE <= 2) {
                int h = n >> 6;
                int hd = n & 63;
                size_t idx = ((((size_t)(bq * Osz + o) * Hsz + h) * Tsz + t) * HDsz) + hd;
                C[idx] = val;
            } else {
                C[(size_t)m * Dsz + n] = val;
            }
        }
    }
}

// ---------------------------------------------------------------------------
// Attention: one block per (b,o,h); thread i = query row i (T=256 threads).
// Flash-style online softmax over 4 chunks of 64 keys, K/V staged in smem.
// Writes g_att in (b,t,o,d) layout for the O-projection GEMM.
// ---------------------------------------------------------------------------
__global__ __launch_bounds__(256)
void attn_k()
{
    __shared__ float Ks[64][64];
    __shared__ float Vs[64][64];
    __shared__ float mk[256];

    const int blk = blockIdx.x;            // (b*O + o)*H + h
    const int b = blk >> 7;                // / (O*H)=128
    const int o = (blk >> 3) & 15;
    const int h = blk & 7;
    const int tid = threadIdx.x;

    // key mask for this (b, :, o): g_mask[(b*T + t)*O + o]
    mk[tid] = g_mask[((size_t)b * Tsz + tid) * Osz + o];

    const size_t base = (size_t)blk * Tsz * HDsz;   // contiguous (t,hd) slab

    float q[64];
    #pragma unroll
    for (int d = 0; d < 64; d += 4) {
        float4 v = *(const float4*)&g_q[base + (size_t)tid * 64 + d];
        q[d] = v.x; q[d+1] = v.y; q[d+2] = v.z; q[d+3] = v.w;
    }

    float mrun = -1e30f, l = 0.f;
    float acc[64];
    #pragma unroll
    for (int d = 0; d < 64; d++) acc[d] = 0.f;

    for (int c = 0; c < 4; c++) {
        __syncthreads();   // also orders the mk[] stores before first use
        const float4* ksrc = (const float4*)&g_k[base + (size_t)c * 4096];
        const float4* vsrc = (const float4*)&g_v[base + (size_t)c * 4096];
        float4* kdst = (float4*)&Ks[0][0];
        float4* vdst = (float4*)&Vs[0][0];
        #pragma unroll
        for (int i = 0; i < 4; i++) {
            kdst[tid + 256 * i] = ksrc[tid + 256 * i];
            vdst[tid + 256 * i] = vsrc[tid + 256 * i];
        }
        __syncthreads();

        for (int j = 0; j < 64; j++) {
            if (mk[c * 64 + j] == 0.f) continue;   // block-uniform branch
            float s = 0.f;
            #pragma unroll
            for (int d = 0; d < 64; d++) s = fmaf(q[d], Ks[j][d], s);
            s *= 0.125f;                           // 1/sqrt(64)
            float mn = fmaxf(mrun, s);
            float alpha = __expf(mrun - mn);
            float p = __expf(s - mn);
            l = l * alpha + p;
            #pragma unroll
            for (int d = 0; d < 64; d++)
                acc[d] = fmaf(acc[d], alpha, p * Vs[j][d]);
            mrun = mn;
        }
    }

    float inv = (l > 0.f) ? (1.f / l) : 0.f;
    // write (b,t,o,d) with d = h*64 + hd
    size_t orow = (((size_t)b * Tsz + tid) * Osz + o) * (size_t)Dsz + (size_t)h * 64;
    #pragma unroll
    for (int d = 0; d < 64; d += 4) {
        float4 v;
        v.x = acc[d + 0] * inv;
        v.y = acc[d + 1] * inv;
        v.z = acc[d + 2] * inv;
        v.w = acc[d + 3] * inv;
        *(float4*)&g_att[orow + d] = v;
    }
}

// ---------------------------------------------------------------------------
// Residual + LayerNorm + output mask. One block per (b,t,o) row, 256 threads,
// 2 elements per thread.
// ---------------------------------------------------------------------------
__global__ __launch_bounds__(256)
void ln_k(const float* __restrict__ x,
          const float* __restrict__ gamma,
          const float* __restrict__ beta,
          float* __restrict__ y)
{
    __shared__ float s1[8], s2[8];
    __shared__ float stats[2];

    const int row = blockIdx.x;
    const int tid = threadIdx.x;
    const size_t base = (size_t)row * Dsz;

    float r0 = g_out[base + tid]       + x[base + tid];
    float r1 = g_out[base + 256 + tid] + x[base + 256 + tid];

    float s = r0 + r1;
    float ss = r0 * r0 + r1 * r1;
    #pragma unroll
    for (int off = 16; off > 0; off >>= 1) {
        s  += __shfl_down_sync(0xffffffffu, s, off);
        ss += __shfl_down_sync(0xffffffffu, ss, off);
    }
    if ((tid & 31) == 0) { s1[tid >> 5] = s; s2[tid >> 5] = ss; }
    __syncthreads();
    if (tid == 0) {
        float a = 0.f, b2 = 0.f;
        #pragma unroll
        for (int i = 0; i < 8; i++) { a += s1[i]; b2 += s2[i]; }
        stats[0] = a; stats[1] = b2;
    }
    __syncthreads();

    float mean = stats[0] * (1.f / 512.f);
    float var  = stats[1] * (1.f / 512.f) - mean * mean;
    float rstd = rsqrtf(var + 1e-5f);
    float mf = g_mask[row];

    y[base + tid]       = ((r0 - mean) * rstd * gamma[tid]       + beta[tid])       * mf;
    y[base + 256 + tid] = ((r1 - mean) * rstd * gamma[256 + tid] + beta[256 + tid]) * mf;
}

// ---------------------------------------------------------------------------
// Launch
// ---------------------------------------------------------------------------
extern "C" void kernel_launch(void* const* d_in, const int* in_sizes, int n_in,
                              void* d_out, int out_size)
{
    const float* x   = (const float*)d_in[0];
    const void* mask = d_in[1];
    const float* Wq = (const float*)d_in[2];
    const float* bq = (const float*)d_in[3];
    const float* Wk = (const float*)d_in[4];
    const float* bk = (const float*)d_in[5];
    const float* Wv = (const float*)d_in[6];
    const float* bv = (const float*)d_in[7];
    const float* Wo = (const float*)d_in[8];
    const float* bo = (const float*)d_in[9];
    const float* gamma = (const float*)d_in[10];
    const float* beta  = (const float*)d_in[11];
    float* y = (float*)d_out;

    mask_norm_k<<<1, 1024>>>(mask);

    dim3 gg(Dsz / 128, Mrows / 128);   // (4, 256)
    gemm_k<0><<<gg, 256>>>(x, Wq, bq);
    gemm_k<1><<<gg, 256>>>(x, Wk, bk);
    gemm_k<2><<<gg, 256>>>(x, Wv, bv);
    attn_k<<<Bsz * Osz * Hsz, 256>>>();           // 1024 blocks
    gemm_k<3><<<gg, 256>>>(nullptr, Wo, bo);
    ln_k<<<Mrows, 256>>>(x, gamma, beta, y);
}

// round 3
// speedup vs baseline: 2.3133x; 2.3133x over previous
#include <cuda_runtime.h>
#include <cuda_bf16.h>
#include <cstdint>

// Problem constants
#define Bsz  8
#define Tsz  256
#define Osz  16
#define Dsz  512
#define Hsz  8
#define HDsz 64
#define Mrows (Bsz*Tsz*Osz)      // 32768
#define ELEMS (Mrows*Dsz)        // 16777216
#define WSEG  (Dsz*Dsz)          // 262144

// ---------------------------------------------------------------------------
// Scratch (device globals: no allocation, graph-safe)
// ---------------------------------------------------------------------------
__device__ float g_q[ELEMS];                       // (b,o,h,t,hd)
__device__ float g_k[ELEMS];
__device__ float g_v[ELEMS];
__device__ float g_out[ELEMS];                     // (b,t,o,d)
__device__ float g_mask[Mrows];
__device__ __align__(16) __nv_bfloat16 g_xhi[ELEMS];   // X split (b,t,o,d)
__device__ __align__(16) __nv_bfloat16 g_xlo[ELEMS];
__device__ __align__(16) __nv_bfloat16 g_ahi[ELEMS];   // att split (b,t,o,d)
__device__ __align__(16) __nv_bfloat16 g_alo[ELEMS];
__device__ __align__(16) __nv_bfloat16 g_whi[4*WSEG];  // Wq,Wk,Wv,Wo split
__device__ __align__(16) __nv_bfloat16 g_wlo[4*WSEG];

// ---------------------------------------------------------------------------
// PTX helpers
// ---------------------------------------------------------------------------
__device__ __forceinline__ void cp16(uint32_t dst, const void* src) {
    asm volatile("cp.async.cg.shared.global [%0], [%1], 16;" :: "r"(dst), "l"(src));
}
__device__ __forceinline__ void ldsm4(unsigned (&r)[4], uint32_t addr) {
    asm volatile("ldmatrix.sync.aligned.m8n8.x4.shared.b16 {%0,%1,%2,%3}, [%4];"
                 : "=r"(r[0]), "=r"(r[1]), "=r"(r[2]), "=r"(r[3]) : "r"(addr));
}
__device__ __forceinline__ void ldsm4t(unsigned& r0, unsigned& r1, unsigned& r2, unsigned& r3, uint32_t addr) {
    asm volatile("ldmatrix.sync.aligned.m8n8.x4.trans.shared.b16 {%0,%1,%2,%3}, [%4];"
                 : "=r"(r0), "=r"(r1), "=r"(r2), "=r"(r3) : "r"(addr));
}
__device__ __forceinline__ void mma_bf16(float (&d)[4], const unsigned (&a)[4], unsigned b0, unsigned b1) {
    asm volatile("mma.sync.aligned.m16n8k16.row.col.f32.bf16.bf16.f32 "
                 "{%0,%1,%2,%3}, {%4,%5,%6,%7}, {%8,%9}, {%0,%1,%2,%3};"
                 : "+f"(d[0]), "+f"(d[1]), "+f"(d[2]), "+f"(d[3])
                 : "r"(a[0]), "r"(a[1]), "r"(a[2]), "r"(a[3]), "r"(b0), "r"(b1));
}

// ---------------------------------------------------------------------------
// Mask normalization (harness may marshal bool as int32 or bytes)
// ---------------------------------------------------------------------------
__global__ void mask_norm_k(const void* __restrict__ mraw)
{
    __shared__ int s_bytes;
    const unsigned int*  mi = (const unsigned int*)mraw;
    const unsigned char* mb = (const unsigned char*)mraw;
    if (threadIdx.x == 0) s_bytes = 0;
    __syncthreads();
    for (int i = threadIdx.x; i < Mrows; i += blockDim.x)
        if (mi[i] > 1u) atomicOr(&s_bytes, 1);
    __syncthreads();
    const bool bytes = (s_bytes != 0);
    for (int i = threadIdx.x; i < Mrows; i += blockDim.x)
        g_mask[i] = bytes ? (mb[i] ? 1.f : 0.f) : (mi[i] ? 1.f : 0.f);
}

// ---------------------------------------------------------------------------
// fp32 -> bf16 hi/lo split conversions
// ---------------------------------------------------------------------------
__device__ __forceinline__ void split4(float4 v, uint2& hi, uint2& lo) {
    __nv_bfloat16 h0 = __float2bfloat16(v.x), h1 = __float2bfloat16(v.y);
    __nv_bfloat16 h2 = __float2bfloat16(v.z), h3 = __float2bfloat16(v.w);
    __nv_bfloat16 l0 = __float2bfloat16(v.x - __bfloat162float(h0));
    __nv_bfloat16 l1 = __float2bfloat16(v.y - __bfloat162float(h1));
    __nv_bfloat16 l2 = __float2bfloat16(v.z - __bfloat162float(h2));
    __nv_bfloat16 l3 = __float2bfloat16(v.w - __bfloat162float(h3));
    __nv_bfloat162 hp0(h0, h1), hp1(h2, h3), lp0(l0, l1), lp1(l2, l3);
    hi.x = *(unsigned*)&hp0; hi.y = *(unsigned*)&hp1;
    lo.x = *(unsigned*)&lp0; lo.y = *(unsigned*)&lp1;
}

__global__ void convX_k(const float4* __restrict__ x)
{
    int i = blockIdx.x * blockDim.x + threadIdx.x;   // 4194304 float4
    uint2 hi, lo;
    split4(x[i], hi, lo);
    ((uint2*)g_xhi)[i] = hi;
    ((uint2*)g_xlo)[i] = lo;
}

__global__ void convW_k(const float4* __restrict__ w0, const float4* __restrict__ w1,
                        const float4* __restrict__ w2, const float4* __restrict__ w3)
{
    const float4* src = (blockIdx.y == 0) ? w0 : (blockIdx.y == 1) ? w1 : (blockIdx.y == 2) ? w2 : w3;
    int i = blockIdx.x * blockDim.x + threadIdx.x;   // 65536 float4 per matrix
    uint2 hi, lo;
    split4(src[i], hi, lo);
    size_t off = (size_t)blockIdx.y * (WSEG / 4) + i;
    ((uint2*)g_whi)[off] = hi;
    ((uint2*)g_wlo)[off] = lo;
}

// ---------------------------------------------------------------------------
// Tensor-core GEMM: C[M=32768,N=512] = A @ W + bias, split-bf16 (3 passes).
// Block 128x128, BK=32, 8 warps (warp tile 32x64), cp.async double buffer.
// MODE 0/1/2: A = g_xhi/lo, C = g_q/g_k/g_v (head-major). W seg = MODE.
// MODE 3:     A = g_ahi/lo, C = g_out (row-major).       W seg = 3.
// ---------------------------------------------------------------------------
#define A_STRIDE 40          // bf16 elems per smem row (80 B)
#define B_STRIDE 136         // bf16 elems per smem row (272 B)
#define A_BYTES  (128*A_STRIDE*2)   // 10240
#define B_BYTES  (32*B_STRIDE*2)    // 8704
#define STG_BYTES (2*A_BYTES + 2*B_BYTES)  // 37888
#define SMEM_TOTAL (2*STG_BYTES)           // 75776

template<int MODE>
__global__ __launch_bounds__(256, 2)
void bgemm_k(const float* __restrict__ bias)
{
    const __nv_bfloat16* Ahi = (MODE <= 2) ? g_xhi : g_ahi;
    const __nv_bfloat16* Alo = (MODE <= 2) ? g_xlo : g_alo;
    const __nv_bfloat16* Bhi = g_whi + (size_t)MODE * WSEG;
    const __nv_bfloat16* Blo = g_wlo + (size_t)MODE * WSEG;
    float* C = (MODE == 0) ? g_q : (MODE == 1) ? g_k : (MODE == 2) ? g_v : g_out;

    extern __shared__ char smem[];
    const uint32_t sbase = (uint32_t)__cvta_generic_to_shared(smem);

    const int tid = threadIdx.x;
    const int lane = tid & 31;
    const int wid = tid >> 5;
    const int wm = wid & 3;          // 0..3 -> m offset wm*32
    const int wn = wid >> 2;         // 0..1 -> n offset wn*64
    const int m0 = blockIdx.y * 128;
    const int n0 = blockIdx.x * 128;

    float acc[2][8][4];
    #pragma unroll
    for (int a = 0; a < 2; a++)
        #pragma unroll
        for (int b = 0; b < 8; b++)
            #pragma unroll
            for (int c = 0; c < 4; c++) acc[a][b][c] = 0.f;

    // per-thread copy indices
    const int aid0 = tid * 2;
    // ---- stage copy (lambda-free for reg sanity) ----
    #define COPY_STAGE(I, S)                                                        \
    {                                                                               \
        const int k0 = (I) * 32;                                                    \
        const uint32_t sb = sbase + (S) * STG_BYTES;                                \
        _Pragma("unroll")                                                           \
        for (int c = 0; c < 2; c++) {                                               \
            int id = aid0 + c;                                                      \
            int ar = id >> 2, ac = id & 3;                                          \
            const __nv_bfloat16* gA = Ahi + (size_t)(m0 + ar) * Dsz + k0 + ac * 8;  \
            const __nv_bfloat16* gAl = Alo + (size_t)(m0 + ar) * Dsz + k0 + ac * 8; \
            uint32_t dA = sb + ar * (A_STRIDE*2) + ac * 16;                         \
            cp16(dA, gA);                                                           \
            cp16(dA + A_BYTES, gAl);                                                \
            int br = id >> 4, bc = id & 15;                                         \
            const __nv_bfloat16* gB = Bhi + (size_t)(k0 + br) * Dsz + n0 + bc * 8;  \
            const __nv_bfloat16* gBl = Blo + (size_t)(k0 + br) * Dsz + n0 + bc * 8; \
            uint32_t dB = sb + 2*A_BYTES + br * (B_STRIDE*2) + bc * 16;             \
            cp16(dB, gB);                                                           \
            cp16(dB + B_BYTES, gBl);                                                \
        }                                                                           \
        asm volatile("cp.async.commit_group;");                                     \
    }

    COPY_STAGE(0, 0);

    const int arow = (lane & 7) + ((lane >> 3) & 1) * 8;   // row within m16 tile
    const int asel = (lane >> 4) * 8;                      // k half select
    const int brow = (lane & 7) + ((lane >> 3) & 1) * 8;   // row within k16
    const int bsel = (lane >> 4) * 8;                      // n half select

    for (int i = 0; i < 16; i++) {
        int s = i & 1;
        if (i < 15) { COPY_STAGE(i + 1, s ^ 1); }
        if (i < 15) asm volatile("cp.async.wait_group 1;");
        else        asm volatile("cp.async.wait_group 0;");
        __syncthreads();

        const uint32_t sb   = sbase + s * STG_BYTES;
        const uint32_t sAhi = sb;
        const uint32_t sAlo = sb + A_BYTES;
        const uint32_t sBhi = sb + 2 * A_BYTES;
        const uint32_t sBlo = sBhi + B_BYTES;

        #pragma unroll
        for (int kk = 0; kk < 32; kk += 16) {
            unsigned ah[2][4], al[2][4];
            #pragma unroll
            for (int mt = 0; mt < 2; mt++) {
                uint32_t off = (uint32_t)(wm * 32 + mt * 16 + arow) * (A_STRIDE*2) + (kk + asel) * 2;
                ldsm4(ah[mt], sAhi + off);
                ldsm4(al[mt], sAlo + off);
            }
            #pragma unroll
            for (int p = 0; p < 3; p++) {
                const unsigned (*af)[4] = (p == 2) ? al : ah;
                const uint32_t bbase = (p == 1) ? sBlo : sBhi;
                #pragma unroll
                for (int np = 0; np < 4; np++) {
                    unsigned b0, b1, b2, b3;
                    uint32_t boff = (uint32_t)(kk + brow) * (B_STRIDE*2) + (wn * 64 + np * 16 + bsel) * 2;
                    ldsm4t(b0, b1, b2, b3, bbase + boff);
                    #pragma unroll
                    for (int mt = 0; mt < 2; mt++) {
                        mma_bf16(acc[mt][2*np],     af[mt], b0, b1);
                        mma_bf16(acc[mt][2*np + 1], af[mt], b2, b3);
                    }
                }
            }
        }
        __syncthreads();
    }

    // ---- epilogue ----
    #pragma unroll
    for (int mt = 0; mt < 2; mt++) {
        #pragma unroll
        for (int half = 0; half < 2; half++) {
            int m = m0 + wm * 32 + mt * 16 + (lane >> 2) + half * 8;
            int bq = m >> 12;
            int t  = (m >> 4) & 255;
            int o  = m & 15;
            #pragma unroll
            for (int nt = 0; nt < 8; nt++) {
                int n = n0 + wn * 64 + nt * 8 + (lane & 3) * 2;
                float2 v;
                v.x = acc[mt][nt][half*2 + 0] + bias[n];
                v.y = acc[mt][nt][half*2 + 1] + bias[n + 1];
                if (MODE <= 2) {
                    int h = n >> 6, hd = n & 63;
                    size_t idx = ((((size_t)(bq * Osz + o) * Hsz + h) * Tsz + t) * HDsz) + hd;
                    *(float2*)&C[idx] = v;
                } else {
                    *(float2*)&C[(size_t)m * Dsz + n] = v;
                }
            }
        }
    }
    #undef COPY_STAGE
}

// ---------------------------------------------------------------------------
// Attention: one block per (b,o,h); thread = query row. Writes bf16 hi/lo
// att directly ((b,t,o,d) layout) for the O-projection tensor GEMM.
// ---------------------------------------------------------------------------
__global__ __launch_bounds__(256)
void attn_k()
{
    __shared__ float Ks[64][64];
    __shared__ float Vs[64][64];
    __shared__ float mk[256];

    const int blk = blockIdx.x;            // (b*O + o)*H + h
    const int b = blk >> 7;
    const int o = (blk >> 3) & 15;
    const int h = blk & 7;
    const int tid = threadIdx.x;

    mk[tid] = g_mask[((size_t)b * Tsz + tid) * Osz + o];

    const size_t base = (size_t)blk * Tsz * HDsz;

    float q[64];
    #pragma unroll
    for (int d = 0; d < 64; d += 4) {
        float4 v = *(const float4*)&g_q[base + (size_t)tid * 64 + d];
        q[d] = v.x; q[d+1] = v.y; q[d+2] = v.z; q[d+3] = v.w;
    }

    float mrun = -1e30f, l = 0.f;
    float acc[64];
    #pragma unroll
    for (int d = 0; d < 64; d++) acc[d] = 0.f;

    for (int c = 0; c < 4; c++) {
        __syncthreads();
        const float4* ksrc = (const float4*)&g_k[base + (size_t)c * 4096];
        const float4* vsrc = (const float4*)&g_v[base + (size_t)c * 4096];
        float4* kdst = (float4*)&Ks[0][0];
        float4* vdst = (float4*)&Vs[0][0];
        #pragma unroll
        for (int i = 0; i < 4; i++) {
            kdst[tid + 256 * i] = ksrc[tid + 256 * i];
            vdst[tid + 256 * i] = vsrc[tid + 256 * i];
        }
        __syncthreads();

        for (int j = 0; j < 64; j++) {
            if (mk[c * 64 + j] == 0.f) continue;
            float s = 0.f;
            #pragma unroll
            for (int d = 0; d < 64; d++) s = fmaf(q[d], Ks[j][d], s);
            s *= 0.125f;
            float mn = fmaxf(mrun, s);
            float alpha = __expf(mrun - mn);
            float p = __expf(s - mn);
            l = l * alpha + p;
            #pragma unroll
            for (int d = 0; d < 64; d++)
                acc[d] = fmaf(acc[d], alpha, p * Vs[j][d]);
            mrun = mn;
        }
    }

    float inv = (l > 0.f) ? (1.f / l) : 0.f;
    size_t orow = (((size_t)b * Tsz + tid) * Osz + o) * (size_t)Dsz + (size_t)h * 64;
    #pragma unroll
    for (int d = 0; d < 64; d += 2) {
        float v0 = acc[d] * inv, v1 = acc[d + 1] * inv;
        __nv_bfloat16 h0 = __float2bfloat16(v0), h1 = __float2bfloat16(v1);
        __nv_bfloat16 l0 = __float2bfloat16(v0 - __bfloat162float(h0));
        __nv_bfloat16 l1 = __float2bfloat16(v1 - __bfloat162float(h1));
        *(__nv_bfloat162*)&g_ahi[orow + d] = __nv_bfloat162(h0, h1);
        *(__nv_bfloat162*)&g_alo[orow + d] = __nv_bfloat162(l0, l1);
    }
}

// ---------------------------------------------------------------------------
// Residual + LayerNorm + output mask
// ---------------------------------------------------------------------------
__global__ __launch_bounds__(256)
void ln_k(const float* __restrict__ x,
          const float* __restrict__ gamma,
          const float* __restrict__ beta,
          float* __restrict__ y)
{
    __shared__ float s1[8], s2[8];
    __shared__ float stats[2];

    const int row = blockIdx.x;
    const int tid = threadIdx.x;
    const size_t base = (size_t)row * Dsz;

    float r0 = g_out[base + tid]       + x[base + tid];
    float r1 = g_out[base + 256 + tid] + x[base + 256 + tid];

    float s = r0 + r1;
    float ss = r0 * r0 + r1 * r1;
    #pragma unroll
    for (int off = 16; off > 0; off >>= 1) {
        s  += __shfl_down_sync(0xffffffffu, s, off);
        ss += __shfl_down_sync(0xffffffffu, ss, off);
    }
    if ((tid & 31) == 0) { s1[tid >> 5] = s; s2[tid >> 5] = ss; }
    __syncthreads();
    if (tid == 0) {
        float a = 0.f, b2 = 0.f;
        #pragma unroll
        for (int i = 0; i < 8; i++) { a += s1[i]; b2 += s2[i]; }
        stats[0] = a; stats[1] = b2;
    }
    __syncthreads();

    float mean = stats[0] * (1.f / 512.f);
    float var  = stats[1] * (1.f / 512.f) - mean * mean;
    float rstd = rsqrtf(var + 1e-5f);
    float mf = g_mask[row];

    y[base + tid]       = ((r0 - mean) * rstd * gamma[tid]       + beta[tid])       * mf;
    y[base + 256 + tid] = ((r1 - mean) * rstd * gamma[256 + tid] + beta[256 + tid]) * mf;
}

// ---------------------------------------------------------------------------
// Launch
// ---------------------------------------------------------------------------
extern "C" void kernel_launch(void* const* d_in, const int* in_sizes, int n_in,
                              void* d_out, int out_size)
{
    const float* x   = (const float*)d_in[0];
    const void* mask = d_in[1];
    const float* Wq = (const float*)d_in[2];
    const float* bq = (const float*)d_in[3];
    const float* Wk = (const float*)d_in[4];
    const float* bk = (const float*)d_in[5];
    const float* Wv = (const float*)d_in[6];
    const float* bv = (const float*)d_in[7];
    const float* Wo = (const float*)d_in[8];
    const float* bo = (const float*)d_in[9];
    const float* gamma = (const float*)d_in[10];
    const float* beta  = (const float*)d_in[11];
    float* y = (float*)d_out;

    cudaFuncSetAttribute(bgemm_k<0>, cudaFuncAttributeMaxDynamicSharedMemorySize, SMEM_TOTAL);
    cudaFuncSetAttribute(bgemm_k<1>, cudaFuncAttributeMaxDynamicSharedMemorySize, SMEM_TOTAL);
    cudaFuncSetAttribute(bgemm_k<2>, cudaFuncAttributeMaxDynamicSharedMemorySize, SMEM_TOTAL);
    cudaFuncSetAttribute(bgemm_k<3>, cudaFuncAttributeMaxDynamicSharedMemorySize, SMEM_TOTAL);

    mask_norm_k<<<1, 1024>>>(mask);
    convW_k<<<dim3(256, 4), 256>>>((const float4*)Wq, (const float4*)Wk,
                                   (const float4*)Wv, (const float4*)Wo);
    convX_k<<<ELEMS / 4 / 256, 256>>>((const float4*)x);

    dim3 gg(Dsz / 128, Mrows / 128);   // (4, 256)
    bgemm_k<0><<<gg, 256, SMEM_TOTAL>>>(bq);
    bgemm_k<1><<<gg, 256, SMEM_TOTAL>>>(bk);
    bgemm_k<2><<<gg, 256, SMEM_TOTAL>>>(bv);
    attn_k<<<Bsz * Osz * Hsz, 256>>>();
    bgemm_k<3><<<gg, 256, SMEM_TOTAL>>>(bo);
    ln_k<<<Mrows, 256>>>(x, gamma, beta, y);
}

// round 4
// speedup vs baseline: 3.0168x; 1.3041x over previous
#include <cuda_runtime.h>
#include <cuda_bf16.h>
#include <cstdint>

// Problem constants
#define Bsz  8
#define Tsz  256
#define Osz  16
#define Dsz  512
#define Hsz  8
#define HDsz 64
#define Mrows (Bsz*Tsz*Osz)      // 32768
#define ELEMS (Mrows*Dsz)        // 16777216
#define WSEG  (Dsz*Dsz)          // 262144

// ---------------------------------------------------------------------------
// Scratch (device globals: no allocation, graph-safe)
// ---------------------------------------------------------------------------
__device__ float g_out[ELEMS];                     // (b,t,o,d)
__device__ float g_mask[Mrows];
__device__ __align__(16) __nv_bfloat16 g_xhi[ELEMS];   // X split (b,t,o,d)
__device__ __align__(16) __nv_bfloat16 g_xlo[ELEMS];
__device__ __align__(16) __nv_bfloat16 g_ahi[ELEMS];   // att split (b,t,o,d)
__device__ __align__(16) __nv_bfloat16 g_alo[ELEMS];
__device__ __align__(16) __nv_bfloat16 g_whi[4*WSEG];  // Wq,Wk,Wv,Wo split
__device__ __align__(16) __nv_bfloat16 g_wlo[4*WSEG];
__device__ __align__(16) __nv_bfloat16 g_qhi[ELEMS];   // (b,o,h,t,hd), pre-scaled
__device__ __align__(16) __nv_bfloat16 g_qlo[ELEMS];
__device__ __align__(16) __nv_bfloat16 g_khi[ELEMS];
__device__ __align__(16) __nv_bfloat16 g_klo[ELEMS];
__device__ __align__(16) __nv_bfloat16 g_vhi[ELEMS];
__device__ __align__(16) __nv_bfloat16 g_vlo[ELEMS];

// ---------------------------------------------------------------------------
// PTX helpers
// ---------------------------------------------------------------------------
__device__ __forceinline__ void cp16(uint32_t dst, const void* src) {
    asm volatile("cp.async.cg.shared.global [%0], [%1], 16;" :: "r"(dst), "l"(src));
}
__device__ __forceinline__ void ldsm4(unsigned (&r)[4], uint32_t addr) {
    asm volatile("ldmatrix.sync.aligned.m8n8.x4.shared.b16 {%0,%1,%2,%3}, [%4];"
                 : "=r"(r[0]), "=r"(r[1]), "=r"(r[2]), "=r"(r[3]) : "r"(addr));
}
__device__ __forceinline__ void ldsm4t(unsigned (&r)[4], uint32_t addr) {
    asm volatile("ldmatrix.sync.aligned.m8n8.x4.trans.shared.b16 {%0,%1,%2,%3}, [%4];"
                 : "=r"(r[0]), "=r"(r[1]), "=r"(r[2]), "=r"(r[3]) : "r"(addr));
}
__device__ __forceinline__ void mma_bf16(float (&d)[4], const unsigned (&a)[4], unsigned b0, unsigned b1) {
    asm volatile("mma.sync.aligned.m16n8k16.row.col.f32.bf16.bf16.f32 "
                 "{%0,%1,%2,%3}, {%4,%5,%6,%7}, {%8,%9}, {%0,%1,%2,%3};"
                 : "+f"(d[0]), "+f"(d[1]), "+f"(d[2]), "+f"(d[3])
                 : "r"(a[0]), "r"(a[1]), "r"(a[2]), "r"(a[3]), "r"(b0), "r"(b1));
}
__device__ __forceinline__ unsigned packbf(float a, float b) {
    __nv_bfloat162 h = __floats2bfloat162_rn(a, b);
    return *(unsigned*)&h;
}

// ---------------------------------------------------------------------------
// Mask normalization (harness may marshal bool as int32 or bytes)
// ---------------------------------------------------------------------------
__global__ void mask_norm_k(const void* __restrict__ mraw)
{
    __shared__ int s_bytes;
    const unsigned int*  mi = (const unsigned int*)mraw;
    const unsigned char* mb = (const unsigned char*)mraw;
    if (threadIdx.x == 0) s_bytes = 0;
    __syncthreads();
    for (int i = threadIdx.x; i < Mrows; i += blockDim.x)
        if (mi[i] > 1u) atomicOr(&s_bytes, 1);
    __syncthreads();
    const bool bytes = (s_bytes != 0);
    for (int i = threadIdx.x; i < Mrows; i += blockDim.x)
        g_mask[i] = bytes ? (mb[i] ? 1.f : 0.f) : (mi[i] ? 1.f : 0.f);
}

// ---------------------------------------------------------------------------
// fp32 -> bf16 hi/lo split conversions
// ---------------------------------------------------------------------------
__device__ __forceinline__ void split4(float4 v, uint2& hi, uint2& lo) {
    __nv_bfloat162 h0 = __floats2bfloat162_rn(v.x, v.y);
    __nv_bfloat162 h1 = __floats2bfloat162_rn(v.z, v.w);
    float2 f0 = __bfloat1622float2(h0);
    float2 f1 = __bfloat1622float2(h1);
    __nv_bfloat162 l0 = __floats2bfloat162_rn(v.x - f0.x, v.y - f0.y);
    __nv_bfloat162 l1 = __floats2bfloat162_rn(v.z - f1.x, v.w - f1.y);
    hi.x = *(unsigned*)&h0; hi.y = *(unsigned*)&h1;
    lo.x = *(unsigned*)&l0; lo.y = *(unsigned*)&l1;
}

__global__ void convX_k(const float4* __restrict__ x)
{
    int i = blockIdx.x * blockDim.x + threadIdx.x;
    uint2 hi, lo;
    split4(x[i], hi, lo);
    ((uint2*)g_xhi)[i] = hi;
    ((uint2*)g_xlo)[i] = lo;
}

__global__ void convW_k(const float4* __restrict__ w0, const float4* __restrict__ w1,
                        const float4* __restrict__ w2, const float4* __restrict__ w3)
{
    const float4* src = (blockIdx.y == 0) ? w0 : (blockIdx.y == 1) ? w1 : (blockIdx.y == 2) ? w2 : w3;
    int i = blockIdx.x * blockDim.x + threadIdx.x;
    uint2 hi, lo;
    split4(src[i], hi, lo);
    size_t off = (size_t)blockIdx.y * (WSEG / 4) + i;
    ((uint2*)g_whi)[off] = hi;
    ((uint2*)g_wlo)[off] = lo;
}

// ---------------------------------------------------------------------------
// Tensor-core GEMM: C[M,512] = A @ W + bias, split-bf16 (3 passes).
// MODE 0/1/2: A=X, C=Q/K/V written bf16 hi/lo head-major (Q scaled 0.125)
// MODE 3:     A=att, C=g_out fp32 row-major
// ---------------------------------------------------------------------------
#define A_STRIDE 40
#define B_STRIDE 136
#define A_BYTES  (128*A_STRIDE*2)
#define B_BYTES  (32*B_STRIDE*2)
#define STG_BYTES (2*A_BYTES + 2*B_BYTES)
#define SMEM_TOTAL (2*STG_BYTES)

template<int MODE>
__global__ __launch_bounds__(256, 2)
void bgemm_k(const float* __restrict__ bias)
{
    const __nv_bfloat16* Ahi = (MODE <= 2) ? g_xhi : g_ahi;
    const __nv_bfloat16* Alo = (MODE <= 2) ? g_xlo : g_alo;
    const __nv_bfloat16* Bhi = g_whi + (size_t)MODE * WSEG;
    const __nv_bfloat16* Blo = g_wlo + (size_t)MODE * WSEG;
    __nv_bfloat16* Chi = (MODE == 0) ? g_qhi : (MODE == 1) ? g_khi : g_vhi;
    __nv_bfloat16* Clo = (MODE == 0) ? g_qlo : (MODE == 1) ? g_klo : g_vlo;

    extern __shared__ char smem[];
    const uint32_t sbase = (uint32_t)__cvta_generic_to_shared(smem);

    const int tid = threadIdx.x;
    const int lane = tid & 31;
    const int wid = tid >> 5;
    const int wm = wid & 3;
    const int wn = wid >> 2;
    const int m0 = blockIdx.y * 128;
    const int n0 = blockIdx.x * 128;

    float acc[2][8][4];
    #pragma unroll
    for (int a = 0; a < 2; a++)
        #pragma unroll
        for (int b = 0; b < 8; b++)
            #pragma unroll
            for (int c = 0; c < 4; c++) acc[a][b][c] = 0.f;

    const int aid0 = tid * 2;
    #define COPY_STAGE(I, S)                                                        \
    {                                                                               \
        const int k0 = (I) * 32;                                                    \
        const uint32_t sb = sbase + (S) * STG_BYTES;                                \
        _Pragma("unroll")                                                           \
        for (int c = 0; c < 2; c++) {                                               \
            int id = aid0 + c;                                                      \
            int ar = id >> 2, ac = id & 3;                                          \
            const __nv_bfloat16* gA = Ahi + (size_t)(m0 + ar) * Dsz + k0 + ac * 8;  \
            const __nv_bfloat16* gAl = Alo + (size_t)(m0 + ar) * Dsz + k0 + ac * 8; \
            uint32_t dA = sb + ar * (A_STRIDE*2) + ac * 16;                         \
            cp16(dA, gA);                                                           \
            cp16(dA + A_BYTES, gAl);                                                \
            int br = id >> 4, bc = id & 15;                                         \
            const __nv_bfloat16* gB = Bhi + (size_t)(k0 + br) * Dsz + n0 + bc * 8;  \
            const __nv_bfloat16* gBl = Blo + (size_t)(k0 + br) * Dsz + n0 + bc * 8; \
            uint32_t dB = sb + 2*A_BYTES + br * (B_STRIDE*2) + bc * 16;             \
            cp16(dB, gB);                                                           \
            cp16(dB + B_BYTES, gBl);                                                \
        }                                                                           \
        asm volatile("cp.async.commit_group;");                                     \
    }

    COPY_STAGE(0, 0);

    for (int i = 0; i < 16; i++) {
        int s = i & 1;
        if (i < 15) { COPY_STAGE(i + 1, s ^ 1); }
        if (i < 15) asm volatile("cp.async.wait_group 1;");
        else        asm volatile("cp.async.wait_group 0;");
        __syncthreads();

        const uint32_t sb   = sbase + s * STG_BYTES;
        const uint32_t sAhi = sb;
        const uint32_t sAlo = sb + A_BYTES;
        const uint32_t sBhi = sb + 2 * A_BYTES;
        const uint32_t sBlo = sBhi + B_BYTES;

        #pragma unroll
        for (int kk = 0; kk < 32; kk += 16) {
            unsigned ah[2][4], al[2][4];
            #pragma unroll
            for (int mt = 0; mt < 2; mt++) {
                uint32_t off = (uint32_t)(wm * 32 + mt * 16 + (lane & 15)) * (A_STRIDE*2)
                             + (kk + (lane >> 4) * 8) * 2;
                ldsm4(ah[mt], sAhi + off);
                ldsm4(al[mt], sAlo + off);
            }
            #pragma unroll
            for (int nn = 0; nn < 64; nn += 16) {
                unsigned bh[4], bl[4];
                uint32_t boff = (uint32_t)(kk + (lane & 15)) * (B_STRIDE*2)
                              + (wn * 64 + nn + (lane >> 4) * 8) * 2;
                ldsm4t(bh, sBhi + boff);
                ldsm4t(bl, sBlo + boff);
                #pragma unroll
                for (int mt = 0; mt < 2; mt++) {
                    #pragma unroll
                    for (int t = 0; t < 2; t++) {
                        mma_bf16(acc[mt][nn/8 + t], ah[mt], bh[2*t], bh[2*t+1]);
                        mma_bf16(acc[mt][nn/8 + t], al[mt], bh[2*t], bh[2*t+1]);
                        mma_bf16(acc[mt][nn/8 + t], ah[mt], bl[2*t], bl[2*t+1]);
                    }
                }
            }
        }
        __syncthreads();
    }

    // epilogue
    #pragma unroll
    for (int mt = 0; mt < 2; mt++) {
        #pragma unroll
        for (int half = 0; half < 2; half++) {
            int m = m0 + wm * 32 + mt * 16 + (lane >> 2) + half * 8;
            int bq = m >> 12;
            int t  = (m >> 4) & 255;
            int o  = m & 15;
            #pragma unroll
            for (int nt = 0; nt < 8; nt++) {
                int n = n0 + wn * 64 + nt * 8 + (lane & 3) * 2;
                float2 v;
                v.x = acc[mt][nt][half*2 + 0] + bias[n];
                v.y = acc[mt][nt][half*2 + 1] + bias[n + 1];
                if (MODE <= 2) {
                    if (MODE == 0) { v.x *= 0.125f; v.y *= 0.125f; }
                    __nv_bfloat162 hv = __floats2bfloat162_rn(v.x, v.y);
                    float2 hb = __bfloat1622float2(hv);
                    __nv_bfloat162 lv = __floats2bfloat162_rn(v.x - hb.x, v.y - hb.y);
                    int h = n >> 6, hd = n & 63;
                    size_t idx = ((((size_t)(bq * Osz + o) * Hsz + h) * Tsz + t) * HDsz) + hd;
                    *(__nv_bfloat162*)&Chi[idx] = hv;
                    *(__nv_bfloat162*)&Clo[idx] = lv;
                } else {
                    *(float2*)&g_out[(size_t)m * Dsz + n] = v;
                }
            }
        }
    }
    #undef COPY_STAGE
}

// ---------------------------------------------------------------------------
// Tensor-core flash attention. 1 CTA per (b,o,h), 8 warps, warp tile = 32 rows.
// S = Q K^T (3-pass split bf16), fp32 softmax in frags, O = P V (3-pass).
// ---------------------------------------------------------------------------
#define QSTR 144                         // 72 bf16 * 2B per smem row
#define AQHI 0
#define AQLO (256*QSTR)                  // 36864
#define AKHI (2*256*QSTR)                // 73728
#define AKLO (AKHI + 64*QSTR)
#define AVHI (AKLO + 64*QSTR)
#define AVLO (AVHI + 64*QSTR)
#define AMK  (AVLO + 64*QSTR)            // 110592
#define ATT_SMEM (AMK + 256*4)           // 111616

__global__ __launch_bounds__(256, 1)
void attn_k()
{
    extern __shared__ char sm[];
    const uint32_t sb = (uint32_t)__cvta_generic_to_shared(sm);

    const int blk = blockIdx.x;            // (b*O + o)*H + h
    const int b = blk >> 7;
    const int o = (blk >> 3) & 15;
    const int h = blk & 7;
    const int tid = threadIdx.x;
    const int lane = tid & 31;
    const int w = tid >> 5;
    const int c0 = (lane & 3) * 2;

    const size_t base = (size_t)blk * Tsz * HDsz;

    // mask bias
    ((float*)(sm + AMK))[tid] = (g_mask[((size_t)b * Tsz + tid) * Osz + o] != 0.f) ? 0.f : -1e30f;

    // stage Q (hi/lo) into smem
    #pragma unroll
    for (int i = 0; i < 8; i++) {
        int id = tid + i * 256;
        int r = id >> 3, c = id & 7;
        cp16(sb + AQHI + r * QSTR + c * 16, g_qhi + base + (size_t)r * 64 + c * 8);
        cp16(sb + AQLO + r * QSTR + c * 16, g_qlo + base + (size_t)r * 64 + c * 8);
    }
    asm volatile("cp.async.commit_group;");

    float O[2][8][4];
    #pragma unroll
    for (int a = 0; a < 2; a++)
        #pragma unroll
        for (int n = 0; n < 8; n++)
            #pragma unroll
            for (int c = 0; c < 4; c++) O[a][n][c] = 0.f;
    float mrow[2][2] = {{-1e30f, -1e30f}, {-1e30f, -1e30f}};
    float lrow[2][2] = {{0.f, 0.f}, {0.f, 0.f}};

    for (int kb = 0; kb < 4; kb++) {
        __syncthreads();   // previous block's compute done; smem reusable
        #pragma unroll
        for (int i = 0; i < 2; i++) {
            int id = tid + i * 256;
            int r = id >> 3, c = id & 7;
            size_t gb = base + (size_t)(kb * 64 + r) * 64 + c * 8;
            uint32_t d = r * QSTR + c * 16;
            cp16(sb + AKHI + d, g_khi + gb);
            cp16(sb + AKLO + d, g_klo + gb);
            cp16(sb + AVHI + d, g_vhi + gb);
            cp16(sb + AVLO + d, g_vlo + gb);
        }
        asm volatile("cp.async.commit_group;");
        asm volatile("cp.async.wait_group 0;");
        __syncthreads();

        // ---- S = Q K^T ----
        float s[2][8][4];
        #pragma unroll
        for (int a = 0; a < 2; a++)
            #pragma unroll
            for (int n = 0; n < 8; n++)
                #pragma unroll
                for (int c = 0; c < 4; c++) s[a][n][c] = 0.f;

        #pragma unroll
        for (int kk = 0; kk < 64; kk += 16) {
            unsigned ah[2][4], al[2][4];
            #pragma unroll
            for (int mt = 0; mt < 2; mt++) {
                uint32_t aoff = (uint32_t)(w * 32 + mt * 16 + (lane & 15)) * QSTR
                              + (kk + (lane >> 4) * 8) * 2;
                ldsm4(ah[mt], sb + AQHI + aoff);
                ldsm4(al[mt], sb + AQLO + aoff);
            }
            #pragma unroll
            for (int nn = 0; nn < 64; nn += 16) {
                // non-trans B frags from K[t, hd] (t = n rows)
                int row = nn + ((lane >> 4) << 3) + (lane & 7);
                int kc  = kk + (((lane >> 3) & 1) << 3);
                uint32_t boff = (uint32_t)row * QSTR + kc * 2;
                unsigned bh[4], bl[4];
                ldsm4(bh, sb + AKHI + boff);
                ldsm4(bl, sb + AKLO + boff);
                #pragma unroll
                for (int mt = 0; mt < 2; mt++) {
                    #pragma unroll
                    for (int t = 0; t < 2; t++) {
                        mma_bf16(s[mt][nn/8 + t], ah[mt], bh[2*t], bh[2*t+1]);
                        mma_bf16(s[mt][nn/8 + t], al[mt], bh[2*t], bh[2*t+1]);
                        mma_bf16(s[mt][nn/8 + t], ah[mt], bl[2*t], bl[2*t+1]);
                    }
                }
            }
        }

        // ---- mask bias + online softmax ----
        const float* mkp = (const float*)(sm + AMK) + kb * 64;
        float nm[2][2] = {{mrow[0][0], mrow[0][1]}, {mrow[1][0], mrow[1][1]}};
        #pragma unroll
        for (int n8 = 0; n8 < 8; n8++) {
            float b0 = mkp[n8 * 8 + c0];
            float b1 = mkp[n8 * 8 + c0 + 1];
            #pragma unroll
            for (int mt = 0; mt < 2; mt++) {
                s[mt][n8][0] += b0; s[mt][n8][1] += b1;
                s[mt][n8][2] += b0; s[mt][n8][3] += b1;
                nm[mt][0] = fmaxf(nm[mt][0], fmaxf(s[mt][n8][0], s[mt][n8][1]));
                nm[mt][1] = fmaxf(nm[mt][1], fmaxf(s[mt][n8][2], s[mt][n8][3]));
            }
        }
        #pragma unroll
        for (int mt = 0; mt < 2; mt++)
            #pragma unroll
            for (int hf = 0; hf < 2; hf++) {
                float v = nm[mt][hf];
                v = fmaxf(v, __shfl_xor_sync(0xffffffffu, v, 1));
                v = fmaxf(v, __shfl_xor_sync(0xffffffffu, v, 2));
                nm[mt][hf] = v;
            }

        float rs[2][2] = {{0.f, 0.f}, {0.f, 0.f}};
        #pragma unroll
        for (int mt = 0; mt < 2; mt++)
            #pragma unroll
            for (int n8 = 0; n8 < 8; n8++) {
                float p0 = __expf(s[mt][n8][0] - nm[mt][0]);
                float p1 = __expf(s[mt][n8][1] - nm[mt][0]);
                float p2 = __expf(s[mt][n8][2] - nm[mt][1]);
                float p3 = __expf(s[mt][n8][3] - nm[mt][1]);
                s[mt][n8][0] = p0; s[mt][n8][1] = p1;
                s[mt][n8][2] = p2; s[mt][n8][3] = p3;
                rs[mt][0] += p0 + p1;
                rs[mt][1] += p2 + p3;
            }
        float alpha[2][2];
        #pragma unroll
        for (int mt = 0; mt < 2; mt++)
            #pragma unroll
            for (int hf = 0; hf < 2; hf++) {
                float v = rs[mt][hf];
                v += __shfl_xor_sync(0xffffffffu, v, 1);
                v += __shfl_xor_sync(0xffffffffu, v, 2);
                float al = __expf(mrow[mt][hf] - nm[mt][hf]);
                lrow[mt][hf] = lrow[mt][hf] * al + v;
                mrow[mt][hf] = nm[mt][hf];
                alpha[mt][hf] = al;
            }
        #pragma unroll
        for (int mt = 0; mt < 2; mt++)
            #pragma unroll
            for (int n8 = 0; n8 < 8; n8++) {
                O[mt][n8][0] *= alpha[mt][0]; O[mt][n8][1] *= alpha[mt][0];
                O[mt][n8][2] *= alpha[mt][1]; O[mt][n8][3] *= alpha[mt][1];
            }

        // ---- O += P V ----
        #pragma unroll
        for (int j = 0; j < 4; j++) {       // k16 chunk of keys
            unsigned pa_hi[2][4], pa_lo[2][4];
            #pragma unroll
            for (int mt = 0; mt < 2; mt++) {
                #pragma unroll
                for (int q = 0; q < 2; q++) {       // the two n8 frags forming k16
                    float p0 = s[mt][2*j + q][0], p1 = s[mt][2*j + q][1];
                    float p2 = s[mt][2*j + q][2], p3 = s[mt][2*j + q][3];
                    unsigned h0 = packbf(p0, p1);
                    unsigned h1 = packbf(p2, p3);
                    float2 f0 = __bfloat1622float2(*(__nv_bfloat162*)&h0);
                    float2 f1 = __bfloat1622float2(*(__nv_bfloat162*)&h1);
                    pa_hi[mt][2*q]   = h0;
                    pa_hi[mt][2*q+1] = h1;
                    pa_lo[mt][2*q]   = packbf(p0 - f0.x, p1 - f0.y);
                    pa_lo[mt][2*q+1] = packbf(p2 - f1.x, p3 - f1.y);
                }
            }
            #pragma unroll
            for (int nn = 0; nn < 64; nn += 16) {
                uint32_t boff = (uint32_t)(j * 16 + (lane & 15)) * QSTR
                              + (nn + (lane >> 4) * 8) * 2;
                unsigned vh[4], vl[4];
                ldsm4t(vh, sb + AVHI + boff);
                ldsm4t(vl, sb + AVLO + boff);
                #pragma unroll
                for (int mt = 0; mt < 2; mt++) {
                    #pragma unroll
                    for (int t = 0; t < 2; t++) {
                        mma_bf16(O[mt][nn/8 + t], pa_hi[mt], vh[2*t], vh[2*t+1]);
                        mma_bf16(O[mt][nn/8 + t], pa_lo[mt], vh[2*t], vh[2*t+1]);
                        mma_bf16(O[mt][nn/8 + t], pa_hi[mt], vl[2*t], vl[2*t+1]);
                    }
                }
            }
        }
    }

    // ---- epilogue: normalize, split bf16, write (b,t,o,d) ----
    float inv[2][2];
    #pragma unroll
    for (int mt = 0; mt < 2; mt++)
        #pragma unroll
        for (int hf = 0; hf < 2; hf++)
            inv[mt][hf] = (mrow[mt][hf] > -1e29f && lrow[mt][hf] > 0.f)
                        ? (1.f / lrow[mt][hf]) : 0.f;

    #pragma unroll
    for (int mt = 0; mt < 2; mt++) {
        #pragma unroll
        for (int hf = 0; hf < 2; hf++) {
            int t = w * 32 + mt * 16 + (lane >> 2) + hf * 8;
            size_t orow = (((size_t)b * Tsz + t) * Osz + o) * (size_t)Dsz + (size_t)h * 64;
            #pragma unroll
            for (int n8 = 0; n8 < 8; n8++) {
                float v0 = O[mt][n8][hf*2 + 0] * inv[mt][hf];
                float v1 = O[mt][n8][hf*2 + 1] * inv[mt][hf];
                unsigned hv = packbf(v0, v1);
                float2 hb = __bfloat1622float2(*(__nv_bfloat162*)&hv);
                unsigned lv = packbf(v0 - hb.x, v1 - hb.y);
                size_t idx = orow + n8 * 8 + c0;
                *(unsigned*)&g_ahi[idx] = hv;
                *(unsigned*)&g_alo[idx] = lv;
            }
        }
    }
}

// ---------------------------------------------------------------------------
// Residual + LayerNorm + output mask
// ---------------------------------------------------------------------------
__global__ __launch_bounds__(256)
void ln_k(const float* __restrict__ x,
          const float* __restrict__ gamma,
          const float* __restrict__ beta,
          float* __restrict__ y)
{
    __shared__ float s1[8], s2[8];
    __shared__ float stats[2];

    const int row = blockIdx.x;
    const int tid = threadIdx.x;
    const size_t base = (size_t)row * Dsz;

    float r0 = g_out[base + tid]       + x[base + tid];
    float r1 = g_out[base + 256 + tid] + x[base + 256 + tid];

    float s = r0 + r1;
    float ss = r0 * r0 + r1 * r1;
    #pragma unroll
    for (int off = 16; off > 0; off >>= 1) {
        s  += __shfl_down_sync(0xffffffffu, s, off);
        ss += __shfl_down_sync(0xffffffffu, ss, off);
    }
    if ((tid & 31) == 0) { s1[tid >> 5] = s; s2[tid >> 5] = ss; }
    __syncthreads();
    if (tid == 0) {
        float a = 0.f, b2 = 0.f;
        #pragma unroll
        for (int i = 0; i < 8; i++) { a += s1[i]; b2 += s2[i]; }
        stats[0] = a; stats[1] = b2;
    }
    __syncthreads();

    float mean = stats[0] * (1.f / 512.f);
    float var  = stats[1] * (1.f / 512.f) - mean * mean;
    float rstd = rsqrtf(var + 1e-5f);
    float mf = g_mask[row];

    y[base + tid]       = ((r0 - mean) * rstd * gamma[tid]       + beta[tid])       * mf;
    y[base + 256 + tid] = ((r1 - mean) * rstd * gamma[256 + tid] + beta[256 + tid]) * mf;
}

// ---------------------------------------------------------------------------
// Launch
// ---------------------------------------------------------------------------
extern "C" void kernel_launch(void* const* d_in, const int* in_sizes, int n_in,
                              void* d_out, int out_size)
{
    const float* x   = (const float*)d_in[0];
    const void* mask = d_in[1];
    const float* Wq = (const float*)d_in[2];
    const float* bq = (const float*)d_in[3];
    const float* Wk = (const float*)d_in[4];
    const float* bk = (const float*)d_in[5];
    const float* Wv = (const float*)d_in[6];
    const float* bv = (const float*)d_in[7];
    const float* Wo = (const float*)d_in[8];
    const float* bo = (const float*)d_in[9];
    const float* gamma = (const float*)d_in[10];
    const float* beta  = (const float*)d_in[11];
    float* y = (float*)d_out;

    cudaFuncSetAttribute(bgemm_k<0>, cudaFuncAttributeMaxDynamicSharedMemorySize, SMEM_TOTAL);
    cudaFuncSetAttribute(bgemm_k<1>, cudaFuncAttributeMaxDynamicSharedMemorySize, SMEM_TOTAL);
    cudaFuncSetAttribute(bgemm_k<2>, cudaFuncAttributeMaxDynamicSharedMemorySize, SMEM_TOTAL);
    cudaFuncSetAttribute(bgemm_k<3>, cudaFuncAttributeMaxDynamicSharedMemorySize, SMEM_TOTAL);
    cudaFuncSetAttribute(attn_k, cudaFuncAttributeMaxDynamicSharedMemorySize, ATT_SMEM);

    mask_norm_k<<<1, 1024>>>(mask);
    convW_k<<<dim3(256, 4), 256>>>((const float4*)Wq, (const float4*)Wk,
                                   (const float4*)Wv, (const float4*)Wo);
    convX_k<<<ELEMS / 4 / 256, 256>>>((const float4*)x);

    dim3 gg(Dsz / 128, Mrows / 128);   // (4, 256)
    bgemm_k<0><<<gg, 256, SMEM_TOTAL>>>(bq);
    bgemm_k<1><<<gg, 256, SMEM_TOTAL>>>(bk);
    bgemm_k<2><<<gg, 256, SMEM_TOTAL>>>(bv);
    attn_k<<<Bsz * Osz * Hsz, 256, ATT_SMEM>>>();
    bgemm_k<3><<<gg, 256, SMEM_TOTAL>>>(bo);
    ln_k<<<Mrows, 256>>>(x, gamma, beta, y);
}

// round 6
// speedup vs baseline: 3.3649x; 1.1154x over previous
#include <cuda_runtime.h>
#include <cuda_bf16.h>
#include <cstdint>

// Problem constants
#define Bsz  8
#define Tsz  256
#define Osz  16
#define Dsz  512
#define Hsz  8
#define HDsz 64
#define Mrows (Bsz*Tsz*Osz)      // 32768
#define ELEMS (Mrows*Dsz)        // 16777216
#define WSEG  (Dsz*Dsz)          // 262144

// ---------------------------------------------------------------------------
// Scratch (device globals: no allocation, graph-safe)
// ---------------------------------------------------------------------------
__device__ float g_out[ELEMS];                     // (b,t,o,d)
__device__ float g_mask[Mrows];
__device__ __align__(16) __nv_bfloat16 g_xhi[ELEMS];   // X split (b,t,o,d)
__device__ __align__(16) __nv_bfloat16 g_xlo[ELEMS];
__device__ __align__(16) __nv_bfloat16 g_ahi[ELEMS];   // att split (b,t,o,d)
__device__ __align__(16) __nv_bfloat16 g_alo[ELEMS];
__device__ __align__(16) __nv_bfloat16 g_whi[4*WSEG];  // Wq,Wk,Wv,Wo split [k][n]
__device__ __align__(16) __nv_bfloat16 g_wlo[4*WSEG];
__device__ __align__(16) __nv_bfloat16 g_qhi[ELEMS];   // (b,o,h,t,hd), pre-scaled
__device__ __align__(16) __nv_bfloat16 g_qlo[ELEMS];
__device__ __align__(16) __nv_bfloat16 g_khi[ELEMS];
__device__ __align__(16) __nv_bfloat16 g_klo[ELEMS];
__device__ __align__(16) __nv_bfloat16 g_vhi[ELEMS];
__device__ __align__(16) __nv_bfloat16 g_vlo[ELEMS];

// ---------------------------------------------------------------------------
// PTX helpers
// ---------------------------------------------------------------------------
__device__ __forceinline__ void cp16(uint32_t dst, const void* src) {
    asm volatile("cp.async.cg.shared.global [%0], [%1], 16;" :: "r"(dst), "l"(src));
}
__device__ __forceinline__ void ldsm4(unsigned (&r)[4], uint32_t addr) {
    asm volatile("ldmatrix.sync.aligned.m8n8.x4.shared.b16 {%0,%1,%2,%3}, [%4];"
                 : "=r"(r[0]), "=r"(r[1]), "=r"(r[2]), "=r"(r[3]) : "r"(addr));
}
__device__ __forceinline__ void ldsm4t(unsigned (&r)[4], uint32_t addr) {
    asm volatile("ldmatrix.sync.aligned.m8n8.x4.trans.shared.b16 {%0,%1,%2,%3}, [%4];"
                 : "=r"(r[0]), "=r"(r[1]), "=r"(r[2]), "=r"(r[3]) : "r"(addr));
}
__device__ __forceinline__ void mma_bf16(float (&d)[4], const unsigned (&a)[4], unsigned b0, unsigned b1) {
    asm volatile("mma.sync.aligned.m16n8k16.row.col.f32.bf16.bf16.f32 "
                 "{%0,%1,%2,%3}, {%4,%5,%6,%7}, {%8,%9}, {%0,%1,%2,%3};"
                 : "+f"(d[0]), "+f"(d[1]), "+f"(d[2]), "+f"(d[3])
                 : "r"(a[0]), "r"(a[1]), "r"(a[2]), "r"(a[3]), "r"(b0), "r"(b1));
}
__device__ __forceinline__ unsigned packbf(float a, float b) {
    __nv_bfloat162 h = __floats2bfloat162_rn(a, b);
    return *(unsigned*)&h;
}

// ---------------------------------------------------------------------------
// Mask normalization (harness may marshal bool as int32 or bytes)
// ---------------------------------------------------------------------------
__global__ void mask_norm_k(const void* __restrict__ mraw)
{
    __shared__ int s_bytes;
    const unsigned int*  mi = (const unsigned int*)mraw;
    const unsigned char* mb = (const unsigned char*)mraw;
    if (threadIdx.x == 0) s_bytes = 0;
    __syncthreads();
    for (int i = threadIdx.x; i < Mrows; i += blockDim.x)
        if (mi[i] > 1u) atomicOr(&s_bytes, 1);
    __syncthreads();
    const bool bytes = (s_bytes != 0);
    for (int i = threadIdx.x; i < Mrows; i += blockDim.x)
        g_mask[i] = bytes ? (mb[i] ? 1.f : 0.f) : (mi[i] ? 1.f : 0.f);
}

// ---------------------------------------------------------------------------
// fp32 -> bf16 hi/lo split conversions
// ---------------------------------------------------------------------------
__device__ __forceinline__ void split4(float4 v, uint2& hi, uint2& lo) {
    __nv_bfloat162 h0 = __floats2bfloat162_rn(v.x, v.y);
    __nv_bfloat162 h1 = __floats2bfloat162_rn(v.z, v.w);
    float2 f0 = __bfloat1622float2(h0);
    float2 f1 = __bfloat1622float2(h1);
    __nv_bfloat162 l0 = __floats2bfloat162_rn(v.x - f0.x, v.y - f0.y);
    __nv_bfloat162 l1 = __floats2bfloat162_rn(v.z - f1.x, v.w - f1.y);
    hi.x = *(unsigned*)&h0; hi.y = *(unsigned*)&h1;
    lo.x = *(unsigned*)&l0; lo.y = *(unsigned*)&l1;
}

__global__ void convX_k(const float4* __restrict__ x)
{
    int i = blockIdx.x * blockDim.x + threadIdx.x;
    uint2 hi, lo;
    split4(x[i], hi, lo);
    ((uint2*)g_xhi)[i] = hi;
    ((uint2*)g_xlo)[i] = lo;
}

__global__ void convW_k(const float4* __restrict__ w0, const float4* __restrict__ w1,
                        const float4* __restrict__ w2, const float4* __restrict__ w3)
{
    const float4* src = (blockIdx.y == 0) ? w0 : (blockIdx.y == 1) ? w1 : (blockIdx.y == 2) ? w2 : w3;
    int i = blockIdx.x * blockDim.x + threadIdx.x;
    uint2 hi, lo;
    split4(src[i], hi, lo);
    size_t off = (size_t)blockIdx.y * (WSEG / 4) + i;
    ((uint2*)g_whi)[off] = hi;
    ((uint2*)g_wlo)[off] = lo;
}

// ---------------------------------------------------------------------------
// Tensor-core GEMM (mma.sync, split-bf16 3 passes), 3-stage cp.async pipeline.
// Block 128x128, BK=32, 8 warps (warp tile 32x64).
// MODE 0: fused QKV — blockIdx.z in {0,1,2} selects matrix; A = X splits,
//         C = Q/K/V bf16 hi/lo head-major (Q scaled 0.125).
// MODE 3: A = att splits, C = g_out fp32 row-major.
// ---------------------------------------------------------------------------
#define A_STRIDE 40
#define B_STRIDE 136
#define A_BYTES  (128*A_STRIDE*2)          // 10240
#define B_BYTES  (32*B_STRIDE*2)           // 8704
#define STG_BYTES (2*A_BYTES + 2*B_BYTES)  // 37888
#define SMEM_TOTAL (3*STG_BYTES)           // 113664

template<int MODE>
__global__ __launch_bounds__(256, 2)
void bgemm_k(const float* __restrict__ bias0,
             const float* __restrict__ bias1,
             const float* __restrict__ bias2)
{
    const int z = (MODE == 0) ? blockIdx.z : 3;
    const __nv_bfloat16* Ahi = (MODE == 0) ? g_xhi : g_ahi;
    const __nv_bfloat16* Alo = (MODE == 0) ? g_xlo : g_alo;
    const __nv_bfloat16* Bhi = g_whi + (size_t)z * WSEG;
    const __nv_bfloat16* Blo = g_wlo + (size_t)z * WSEG;
    __nv_bfloat16* Chi = (z == 0) ? g_qhi : (z == 1) ? g_khi : g_vhi;
    __nv_bfloat16* Clo = (z == 0) ? g_qlo : (z == 1) ? g_klo : g_vlo;
    const float* bias = (MODE != 0) ? bias0 : (z == 0) ? bias0 : (z == 1) ? bias1 : bias2;
    const float scl = (MODE == 0 && z == 0) ? 0.125f : 1.f;

    extern __shared__ char smem[];
    const uint32_t sbase = (uint32_t)__cvta_generic_to_shared(smem);

    const int tid = threadIdx.x;
    const int lane = tid & 31;
    const int wid = tid >> 5;
    const int wm = wid & 3;
    const int wn = wid >> 2;
    const int m0 = blockIdx.y * 128;
    const int n0 = blockIdx.x * 128;

    float acc[2][8][4];
    #pragma unroll
    for (int a = 0; a < 2; a++)
        #pragma unroll
        for (int b = 0; b < 8; b++)
            #pragma unroll
            for (int c = 0; c < 4; c++) acc[a][b][c] = 0.f;

    const int aid0 = tid * 2;
    #define COPY_STAGE(I, S)                                                        \
    {                                                                               \
        const int k0 = (I) * 32;                                                    \
        const uint32_t sb = sbase + (S) * STG_BYTES;                                \
        _Pragma("unroll")                                                           \
        for (int c = 0; c < 2; c++) {                                               \
            int id = aid0 + c;                                                      \
            int ar = id >> 2, ac = id & 3;                                          \
            const __nv_bfloat16* gA = Ahi + (size_t)(m0 + ar) * Dsz + k0 + ac * 8;  \
            const __nv_bfloat16* gAl = Alo + (size_t)(m0 + ar) * Dsz + k0 + ac * 8; \
            uint32_t dA = sb + ar * (A_STRIDE*2) + ac * 16;                         \
            cp16(dA, gA);                                                           \
            cp16(dA + A_BYTES, gAl);                                                \
            int br = id >> 4, bc = id & 15;                                         \
            const __nv_bfloat16* gB = Bhi + (size_t)(k0 + br) * Dsz + n0 + bc * 8;  \
            const __nv_bfloat16* gBl = Blo + (size_t)(k0 + br) * Dsz + n0 + bc * 8; \
            uint32_t dB = sb + 2*A_BYTES + br * (B_STRIDE*2) + bc * 16;             \
            cp16(dB, gB);                                                           \
            cp16(dB + B_BYTES, gBl);                                                \
        }                                                                           \
        asm volatile("cp.async.commit_group;");                                     \
    }

    COPY_STAGE(0, 0);
    COPY_STAGE(1, 1);

    for (int i = 0; i < 16; i++) {
        const int s = i % 3;
        if (i < 15) asm volatile("cp.async.wait_group 1;");
        else        asm volatile("cp.async.wait_group 0;");
        __syncthreads();

        const uint32_t sb   = sbase + s * STG_BYTES;
        const uint32_t sAhi = sb;
        const uint32_t sAlo = sb + A_BYTES;
        const uint32_t sBhi = sb + 2 * A_BYTES;
        const uint32_t sBlo = sBhi + B_BYTES;

        #pragma unroll
        for (int kk = 0; kk < 32; kk += 16) {
            unsigned ah[2][4], al[2][4];
            #pragma unroll
            for (int mt = 0; mt < 2; mt++) {
                uint32_t off = (uint32_t)(wm * 32 + mt * 16 + (lane & 15)) * (A_STRIDE*2)
                             + (kk + (lane >> 4) * 8) * 2;
                ldsm4(ah[mt], sAhi + off);
                ldsm4(al[mt], sAlo + off);
            }
            #pragma unroll
            for (int nn = 0; nn < 64; nn += 16) {
                unsigned bh[4], bl[4];
                uint32_t boff = (uint32_t)(kk + (lane & 15)) * (B_STRIDE*2)
                              + (wn * 64 + nn + (lane >> 4) * 8) * 2;
                ldsm4t(bh, sBhi + boff);
                ldsm4t(bl, sBlo + boff);
                #pragma unroll
                for (int mt = 0; mt < 2; mt++) {
                    #pragma unroll
                    for (int t = 0; t < 2; t++) {
                        mma_bf16(acc[mt][nn/8 + t], ah[mt], bh[2*t], bh[2*t+1]);
                        mma_bf16(acc[mt][nn/8 + t], al[mt], bh[2*t], bh[2*t+1]);
                        mma_bf16(acc[mt][nn/8 + t], ah[mt], bl[2*t], bl[2*t+1]);
                    }
                }
            }
        }
        // stage i+2 overwrites buffer (i+2)%3 == (i-1)%3; safe: all threads
        // passed this iteration's barrier after finishing compute(i-1).
        if (i + 2 < 16) { COPY_STAGE(i + 2, (i + 2) % 3); }
    }

    // epilogue
    #pragma unroll
    for (int mt = 0; mt < 2; mt++) {
        #pragma unroll
        for (int half = 0; half < 2; half++) {
            int m = m0 + wm * 32 + mt * 16 + (lane >> 2) + half * 8;
            int bq = m >> 12;
            int t  = (m >> 4) & 255;
            int o  = m & 15;
            #pragma unroll
            for (int nt = 0; nt < 8; nt++) {
                int n = n0 + wn * 64 + nt * 8 + (lane & 3) * 2;
                float2 v;
                v.x = acc[mt][nt][half*2 + 0] + bias[n];
                v.y = acc[mt][nt][half*2 + 1] + bias[n + 1];
                if (MODE == 0) {
                    v.x *= scl; v.y *= scl;
                    unsigned hv = packbf(v.x, v.y);
                    float2 hb = __bfloat1622float2(*(__nv_bfloat162*)&hv);
                    unsigned lv = packbf(v.x - hb.x, v.y - hb.y);
                    int h = n >> 6, hd = n & 63;
                    size_t idx = ((((size_t)(bq * Osz + o) * Hsz + h) * Tsz + t) * HDsz) + hd;
                    *(unsigned*)&Chi[idx] = hv;
                    *(unsigned*)&Clo[idx] = lv;
                } else {
                    *(float2*)&g_out[(size_t)m * Dsz + n] = v;
                }
            }
        }
    }
    #undef COPY_STAGE
}

// ---------------------------------------------------------------------------
// Tensor-core flash attention (mma.sync). 1 CTA per (b,o,h), 8 warps.
// ---------------------------------------------------------------------------
#define QSTR 144
#define AQHI 0
#define AQLO (256*QSTR)
#define AKHI (2*256*QSTR)
#define AKLO (AKHI + 64*QSTR)
#define AVHI (AKLO + 64*QSTR)
#define AVLO (AVHI + 64*QSTR)
#define AMK  (AVLO + 64*QSTR)
#define ATT_SMEM (AMK + 256*4)

__global__ __launch_bounds__(256, 1)
void attn_k()
{
    extern __shared__ char sm[];
    const uint32_t sb = (uint32_t)__cvta_generic_to_shared(sm);

    const int blk = blockIdx.x;
    const int b = blk >> 7;
    const int o = (blk >> 3) & 15;
    const int h = blk & 7;
    const int tid = threadIdx.x;
    const int lane = tid & 31;
    const int w = tid >> 5;
    const int c0 = (lane & 3) * 2;

    const size_t base = (size_t)blk * Tsz * HDsz;

    ((float*)(sm + AMK))[tid] = (g_mask[((size_t)b * Tsz + tid) * Osz + o] != 0.f) ? 0.f : -1e30f;

    #pragma unroll
    for (int i = 0; i < 8; i++) {
        int id = tid + i * 256;
        int r = id >> 3, c = id & 7;
        cp16(sb + AQHI + r * QSTR + c * 16, g_qhi + base + (size_t)r * 64 + c * 8);
        cp16(sb + AQLO + r * QSTR + c * 16, g_qlo + base + (size_t)r * 64 + c * 8);
    }
    asm volatile("cp.async.commit_group;");

    float O[2][8][4];
    #pragma unroll
    for (int a = 0; a < 2; a++)
        #pragma unroll
        for (int n = 0; n < 8; n++)
            #pragma unroll
            for (int c = 0; c < 4; c++) O[a][n][c] = 0.f;
    float mrow[2][2] = {{-1e30f, -1e30f}, {-1e30f, -1e30f}};
    float lrow[2][2] = {{0.f, 0.f}, {0.f, 0.f}};

    for (int kb = 0; kb < 4; kb++) {
        __syncthreads();
        #pragma unroll
        for (int i = 0; i < 2; i++) {
            int id = tid + i * 256;
            int r = id >> 3, c = id & 7;
            size_t gb = base + (size_t)(kb * 64 + r) * 64 + c * 8;
            uint32_t d = r * QSTR + c * 16;
            cp16(sb + AKHI + d, g_khi + gb);
            cp16(sb + AKLO + d, g_klo + gb);
            cp16(sb + AVHI + d, g_vhi + gb);
            cp16(sb + AVLO + d, g_vlo + gb);
        }
        asm volatile("cp.async.commit_group;");
        asm volatile("cp.async.wait_group 0;");
        __syncthreads();

        float s[2][8][4];
        #pragma unroll
        for (int a = 0; a < 2; a++)
            #pragma unroll
            for (int n = 0; n < 8; n++)
                #pragma unroll
                for (int c = 0; c < 4; c++) s[a][n][c] = 0.f;

        #pragma unroll
        for (int kk = 0; kk < 64; kk += 16) {
            unsigned ah[2][4], al[2][4];
            #pragma unroll
            for (int mt = 0; mt < 2; mt++) {
                uint32_t aoff = (uint32_t)(w * 32 + mt * 16 + (lane & 15)) * QSTR
                              + (kk + (lane >> 4) * 8) * 2;
                ldsm4(ah[mt], sb + AQHI + aoff);
                ldsm4(al[mt], sb + AQLO + aoff);
            }
            #pragma unroll
            for (int nn = 0; nn < 64; nn += 16) {
                int row = nn + ((lane >> 4) << 3) + (lane & 7);
                int kc  = kk + (((lane >> 3) & 1) << 3);
                uint32_t boff = (uint32_t)row * QSTR + kc * 2;
                unsigned bh[4], bl[4];
                ldsm4(bh, sb + AKHI + boff);
                ldsm4(bl, sb + AKLO + boff);
                #pragma unroll
                for (int mt = 0; mt < 2; mt++) {
                    #pragma unroll
                    for (int t = 0; t < 2; t++) {
                        mma_bf16(s[mt][nn/8 + t], ah[mt], bh[2*t], bh[2*t+1]);
                        mma_bf16(s[mt][nn/8 + t], al[mt], bh[2*t], bh[2*t+1]);
                        mma_bf16(s[mt][nn/8 + t], ah[mt], bl[2*t], bl[2*t+1]);
                    }
                }
            }
        }

        const float* mkp = (const float*)(sm + AMK) + kb * 64;
        float nm[2][2] = {{mrow[0][0], mrow[0][1]}, {mrow[1][0], mrow[1][1]}};
        #pragma unroll
        for (int n8 = 0; n8 < 8; n8++) {
            float b0 = mkp[n8 * 8 + c0];
            float b1 = mkp[n8 * 8 + c0 + 1];
            #pragma unroll
            for (int mt = 0; mt < 2; mt++) {
                s[mt][n8][0] += b0; s[mt][n8][1] += b1;
                s[mt][n8][2] += b0; s[mt][n8][3] += b1;
                nm[mt][0] = fmaxf(nm[mt][0], fmaxf(s[mt][n8][0], s[mt][n8][1]));
                nm[mt][1] = fmaxf(nm[mt][1], fmaxf(s[mt][n8][2], s[mt][n8][3]));
            }
        }
        #pragma unroll
        for (int mt = 0; mt < 2; mt++)
            #pragma unroll
            for (int hf = 0; hf < 2; hf++) {
                float v = nm[mt][hf];
                v = fmaxf(v, __shfl_xor_sync(0xffffffffu, v, 1));
                v = fmaxf(v, __shfl_xor_sync(0xffffffffu, v, 2));
                nm[mt][hf] = v;
            }

        float rs[2][2] = {{0.f, 0.f}, {0.f, 0.f}};
        #pragma unroll
        for (int mt = 0; mt < 2; mt++)
            #pragma unroll
            for (int n8 = 0; n8 < 8; n8++) {
                float p0 = __expf(s[mt][n8][0] - nm[mt][0]);
                float p1 = __expf(s[mt][n8][1] - nm[mt][0]);
                float p2 = __expf(s[mt][n8][2] - nm[mt][1]);
                float p3 = __expf(s[mt][n8][3] - nm[mt][1]);
                s[mt][n8][0] = p0; s[mt][n8][1] = p1;
                s[mt][n8][2] = p2; s[mt][n8][3] = p3;
                rs[mt][0] += p0 + p1;
                rs[mt][1] += p2 + p3;
            }
        float alpha[2][2];
        #pragma unroll
        for (int mt = 0; mt < 2; mt++)
            #pragma unroll
            for (int hf = 0; hf < 2; hf++) {
                float v = rs[mt][hf];
                v += __shfl_xor_sync(0xffffffffu, v, 1);
                v += __shfl_xor_sync(0xffffffffu, v, 2);
                float al = __expf(mrow[mt][hf] - nm[mt][hf]);
                lrow[mt][hf] = lrow[mt][hf] * al + v;
                mrow[mt][hf] = nm[mt][hf];
                alpha[mt][hf] = al;
            }
        #pragma unroll
        for (int mt = 0; mt < 2; mt++)
            #pragma unroll
            for (int n8 = 0; n8 < 8; n8++) {
                O[mt][n8][0] *= alpha[mt][0]; O[mt][n8][1] *= alpha[mt][0];
                O[mt][n8][2] *= alpha[mt][1]; O[mt][n8][3] *= alpha[mt][1];
            }

        #pragma unroll
        for (int j = 0; j < 4; j++) {
            unsigned pa_hi[2][4], pa_lo[2][4];
            #pragma unroll
            for (int mt = 0; mt < 2; mt++) {
                #pragma unroll
                for (int q = 0; q < 2; q++) {
                    float p0 = s[mt][2*j + q][0], p1 = s[mt][2*j + q][1];
                    float p2 = s[mt][2*j + q][2], p3 = s[mt][2*j + q][3];
                    unsigned h0 = packbf(p0, p1);
                    unsigned h1 = packbf(p2, p3);
                    float2 f0 = __bfloat1622float2(*(__nv_bfloat162*)&h0);
                    float2 f1 = __bfloat1622float2(*(__nv_bfloat162*)&h1);
                    pa_hi[mt][2*q]   = h0;
                    pa_hi[mt][2*q+1] = h1;
                    pa_lo[mt][2*q]   = packbf(p0 - f0.x, p1 - f0.y);
                    pa_lo[mt][2*q+1] = packbf(p2 - f1.x, p3 - f1.y);
                }
            }
            #pragma unroll
            for (int nn = 0; nn < 64; nn += 16) {
                uint32_t boff = (uint32_t)(j * 16 + (lane & 15)) * QSTR
                              + (nn + (lane >> 4) * 8) * 2;
                unsigned vh[4], vl[4];
                ldsm4t(vh, sb + AVHI + boff);
                ldsm4t(vl, sb + AVLO + boff);
                #pragma unroll
                for (int mt = 0; mt < 2; mt++) {
                    #pragma unroll
                    for (int t = 0; t < 2; t++) {
                        mma_bf16(O[mt][nn/8 + t], pa_hi[mt], vh[2*t], vh[2*t+1]);
                        mma_bf16(O[mt][nn/8 + t], pa_lo[mt], vh[2*t], vh[2*t+1]);
                        mma_bf16(O[mt][nn/8 + t], pa_hi[mt], vl[2*t], vl[2*t+1]);
                    }
                }
            }
        }
    }

    float inv[2][2];
    #pragma unroll
    for (int mt = 0; mt < 2; mt++)
        #pragma unroll
        for (int hf = 0; hf < 2; hf++)
            inv[mt][hf] = (mrow[mt][hf] > -1e29f && lrow[mt][hf] > 0.f)
                        ? (1.f / lrow[mt][hf]) : 0.f;

    #pragma unroll
    for (int mt = 0; mt < 2; mt++) {
        #pragma unroll
        for (int hf = 0; hf < 2; hf++) {
            int t = w * 32 + mt * 16 + (lane >> 2) + hf * 8;
            size_t orow = (((size_t)b * Tsz + t) * Osz + o) * (size_t)Dsz + (size_t)h * 64;
            #pragma unroll
            for (int n8 = 0; n8 < 8; n8++) {
                float v0 = O[mt][n8][hf*2 + 0] * inv[mt][hf];
                float v1 = O[mt][n8][hf*2 + 1] * inv[mt][hf];
                unsigned hv = packbf(v0, v1);
                float2 hb = __bfloat1622float2(*(__nv_bfloat162*)&hv);
                unsigned lv = packbf(v0 - hb.x, v1 - hb.y);
                size_t idx = orow + n8 * 8 + c0;
                *(unsigned*)&g_ahi[idx] = hv;
                *(unsigned*)&g_alo[idx] = lv;
            }
        }
    }
}

// ---------------------------------------------------------------------------
// Residual + LayerNorm + output mask (float4-vectorized, 128 threads/row)
// ---------------------------------------------------------------------------
__global__ __launch_bounds__(128)
void ln_k(const float4* __restrict__ x,
          const float4* __restrict__ gamma,
          const float4* __restrict__ beta,
          float4* __restrict__ y)
{
    __shared__ float s1[4], s2[4];
    __shared__ float stats[2];

    const int row = blockIdx.x;
    const int tid = threadIdx.x;
    const size_t base = (size_t)row * 128 + tid;

    float4 a = ((const float4*)g_out)[base];
    float4 xr = x[base];
    float4 r;
    r.x = a.x + xr.x; r.y = a.y + xr.y; r.z = a.z + xr.z; r.w = a.w + xr.w;

    float s = r.x + r.y + r.z + r.w;
    float ss = r.x * r.x + r.y * r.y + r.z * r.z + r.w * r.w;
    #pragma unroll
    for (int off = 16; off > 0; off >>= 1) {
        s  += __shfl_down_sync(0xffffffffu, s, off);
        ss += __shfl_down_sync(0xffffffffu, ss, off);
    }
    if ((tid & 31) == 0) { s1[tid >> 5] = s; s2[tid >> 5] = ss; }
    __syncthreads();
    if (tid == 0) {
        float a2 = 0.f, b2 = 0.f;
        #pragma unroll
        for (int i = 0; i < 4; i++) { a2 += s1[i]; b2 += s2[i]; }
        stats[0] = a2; stats[1] = b2;
    }
    __syncthreads();

    float mean = stats[0] * (1.f / 512.f);
    float var  = stats[1] * (1.f / 512.f) - mean * mean;
    float rstd = rsqrtf(var + 1e-5f);
    float mf = g_mask[row];

    float4 g = gamma[tid], bb = beta[tid];
    float4 out;
    out.x = ((r.x - mean) * rstd * g.x + bb.x) * mf;
    out.y = ((r.y - mean) * rstd * g.y + bb.y) * mf;
    out.z = ((r.z - mean) * rstd * g.z + bb.z) * mf;
    out.w = ((r.w - mean) * rstd * g.w + bb.w) * mf;
    y[base] = out;
}

// ---------------------------------------------------------------------------
// Launch
// ---------------------------------------------------------------------------
extern "C" void kernel_launch(void* const* d_in, const int* in_sizes, int n_in,
                              void* d_out, int out_size)
{
    const float* x   = (const float*)d_in[0];
    const void* mask = d_in[1];
    const float* Wq = (const float*)d_in[2];
    const float* bq = (const float*)d_in[3];
    const float* Wk = (const float*)d_in[4];
    const float* bk = (const float*)d_in[5];
    const float* Wv = (const float*)d_in[6];
    const float* bv = (const float*)d_in[7];
    const float* Wo = (const float*)d_in[8];
    const float* bo = (const float*)d_in[9];
    const float* gamma = (const float*)d_in[10];
    const float* beta  = (const float*)d_in[11];
    float* y = (float*)d_out;

    cudaFuncSetAttribute(bgemm_k<0>, cudaFuncAttributeMaxDynamicSharedMemorySize, SMEM_TOTAL);
    cudaFuncSetAttribute(bgemm_k<3>, cudaFuncAttributeMaxDynamicSharedMemorySize, SMEM_TOTAL);
    cudaFuncSetAttribute(attn_k, cudaFuncAttributeMaxDynamicSharedMemorySize, ATT_SMEM);

    mask_norm_k<<<1, 1024>>>(mask);
    convW_k<<<dim3(256, 4), 256>>>((const float4*)Wq, (const float4*)Wk,
                                   (const float4*)Wv, (const float4*)Wo);
    convX_k<<<ELEMS / 4 / 256, 256>>>((const float4*)x);

    dim3 gqkv(Dsz / 128, Mrows / 128, 3);   // (4, 256, 3) fused QKV
    bgemm_k<0><<<gqkv, 256, SMEM_TOTAL>>>(bq, bk, bv);
    attn_k<<<Bsz * Osz * Hsz, 256, ATT_SMEM>>>();
    dim3 go(Dsz / 128, Mrows / 128);        // (4, 256) O-proj
    bgemm_k<3><<<go, 256, SMEM_TOTAL>>>(bo, bo, bo);
    ln_k<<<Mrows, 128>>>((const float4*)x, (const float4*)gamma,
                         (const float4*)beta, (float4*)y);
}

// round 7
// speedup vs baseline: 5.5476x; 1.6487x over previous
#include <cuda_runtime.h>
#include <cuda_bf16.h>
#include <cstdint>

// Problem constants
#define Bsz  8
#define Tsz  256
#define Osz  16
#define Dsz  512
#define Hsz  8
#define HDsz 64
#define Mrows (Bsz*Tsz*Osz)      // 32768
#define ELEMS (Mrows*Dsz)        // 16777216
#define WSEG  (Dsz*Dsz)          // 262144
#define NGRP  (Bsz*Osz)          // 128

// ---------------------------------------------------------------------------
// Scratch (device globals: no allocation, graph-safe)
// ---------------------------------------------------------------------------
__device__ float g_out[ELEMS];                     // compact rows
__device__ float g_mask[Mrows];
__device__ int   g_cnt[NGRP];
__device__ int   g_gstart[NGRP];
__device__ int   g_Mc;
__device__ int   g_tlist[NGRP*Tsz];
__device__ int   g_rowsrc[Mrows];                  // compact r -> X row index
__device__ int   g_rowbos[Mrows];                  // compact r -> (g<<8)|slot
__device__ __align__(16) __nv_bfloat16 g_xhi[ELEMS];   // X split (full)
__device__ __align__(16) __nv_bfloat16 g_xlo[ELEMS];
__device__ __align__(16) __nv_bfloat16 g_ahi[ELEMS];   // att split (compact rows)
__device__ __align__(16) __nv_bfloat16 g_alo[ELEMS];
__device__ __align__(16) __nv_bfloat16 g_whi[4*WSEG];  // Wq,Wk,Wv,Wo split [k][n]
__device__ __align__(16) __nv_bfloat16 g_wlo[4*WSEG];
__device__ __align__(16) __nv_bfloat16 g_qhi[ELEMS];   // (g,h,slot,hd), pre-scaled
__device__ __align__(16) __nv_bfloat16 g_qlo[ELEMS];
__device__ __align__(16) __nv_bfloat16 g_khi[ELEMS];
__device__ __align__(16) __nv_bfloat16 g_klo[ELEMS];
__device__ __align__(16) __nv_bfloat16 g_vhi[ELEMS];
__device__ __align__(16) __nv_bfloat16 g_vlo[ELEMS];

// ---------------------------------------------------------------------------
// PTX helpers
// ---------------------------------------------------------------------------
__device__ __forceinline__ void cp16(uint32_t dst, const void* src) {
    asm volatile("cp.async.cg.shared.global [%0], [%1], 16;" :: "r"(dst), "l"(src));
}
__device__ __forceinline__ void st16z(uint32_t dst) {
    asm volatile("st.shared.v4.u32 [%0], {%1,%1,%1,%1};" :: "r"(dst), "r"(0u));
}
__device__ __forceinline__ void ldsm4(unsigned (&r)[4], uint32_t addr) {
    asm volatile("ldmatrix.sync.aligned.m8n8.x4.shared.b16 {%0,%1,%2,%3}, [%4];"
                 : "=r"(r[0]), "=r"(r[1]), "=r"(r[2]), "=r"(r[3]) : "r"(addr));
}
__device__ __forceinline__ void ldsm4t(unsigned (&r)[4], uint32_t addr) {
    asm volatile("ldmatrix.sync.aligned.m8n8.x4.trans.shared.b16 {%0,%1,%2,%3}, [%4];"
                 : "=r"(r[0]), "=r"(r[1]), "=r"(r[2]), "=r"(r[3]) : "r"(addr));
}
__device__ __forceinline__ void mma_bf16(float (&d)[4], const unsigned (&a)[4], unsigned b0, unsigned b1) {
    asm volatile("mma.sync.aligned.m16n8k16.row.col.f32.bf16.bf16.f32 "
                 "{%0,%1,%2,%3}, {%4,%5,%6,%7}, {%8,%9}, {%0,%1,%2,%3};"
                 : "+f"(d[0]), "+f"(d[1]), "+f"(d[2]), "+f"(d[3])
                 : "r"(a[0]), "r"(a[1]), "r"(a[2]), "r"(a[3]), "r"(b0), "r"(b1));
}
__device__ __forceinline__ unsigned packbf(float a, float b) {
    __nv_bfloat162 h = __floats2bfloat162_rn(a, b);
    return *(unsigned*)&h;
}

// ---------------------------------------------------------------------------
// Mask normalization + compaction
// ---------------------------------------------------------------------------
__global__ void mask_norm_k(const void* __restrict__ mraw)
{
    __shared__ int s_bytes;
    const unsigned int*  mi = (const unsigned int*)mraw;
    const unsigned char* mb = (const unsigned char*)mraw;
    if (threadIdx.x == 0) s_bytes = 0;
    __syncthreads();
    for (int i = threadIdx.x; i < Mrows; i += blockDim.x)
        if (mi[i] > 1u) atomicOr(&s_bytes, 1);
    __syncthreads();
    const bool bytes = (s_bytes != 0);
    for (int i = threadIdx.x; i < Mrows; i += blockDim.x)
        g_mask[i] = bytes ? (mb[i] ? 1.f : 0.f) : (mi[i] ? 1.f : 0.f);
}

// per-(b,o) compaction: counts + slot->t list
__global__ void comp_scan_k()
{
    const int g = blockIdx.x, b = g >> 4, o = g & 15;
    const int tid = threadIdx.x, lane = tid & 31, w = tid >> 5;
    __shared__ int wtot[8];
    int v = (g_mask[(size_t)(b * Tsz + tid) * Osz + o] != 0.f) ? 1 : 0;
    unsigned bal = __ballot_sync(0xffffffffu, v);
    int pfx = __popc(bal & ((1u << lane) - 1u));
    if (lane == 31) wtot[w] = pfx + v;
    __syncthreads();
    int woff = 0;
    #pragma unroll
    for (int i = 0; i < 8; i++) woff += (i < w) ? wtot[i] : 0;
    if (v) g_tlist[g * Tsz + woff + pfx] = tid;
    if (tid == 255) g_cnt[g] = woff + pfx + v;
}

// exclusive prefix over group counts
__global__ void gstart_k()
{
    __shared__ int tmp[NGRP];
    int tid = threadIdx.x;
    int c = g_cnt[tid];
    tmp[tid] = c;
    __syncthreads();
    for (int off = 1; off < NGRP; off <<= 1) {
        int t = (tid >= off) ? tmp[tid - off] : 0;
        __syncthreads();
        tmp[tid] += t;
        __syncthreads();
    }
    g_gstart[tid] = tmp[tid] - c;
    if (tid == NGRP - 1) g_Mc = tmp[NGRP - 1];
}

// compact row maps
__global__ void rowmap_k()
{
    int g = blockIdx.x, s = threadIdx.x;
    if (s < g_cnt[g]) {
        int t = g_tlist[g * Tsz + s];
        int r = g_gstart[g] + s;
        g_rowsrc[r] = (g >> 4) * (Tsz * Osz) + t * Osz + (g & 15);
        g_rowbos[r] = (g << 8) | s;
    }
}

// ---------------------------------------------------------------------------
// fp32 -> bf16 hi/lo split conversions
// ---------------------------------------------------------------------------
__device__ __forceinline__ void split4(float4 v, uint2& hi, uint2& lo) {
    __nv_bfloat162 h0 = __floats2bfloat162_rn(v.x, v.y);
    __nv_bfloat162 h1 = __floats2bfloat162_rn(v.z, v.w);
    float2 f0 = __bfloat1622float2(h0);
    float2 f1 = __bfloat1622float2(h1);
    __nv_bfloat162 l0 = __floats2bfloat162_rn(v.x - f0.x, v.y - f0.y);
    __nv_bfloat162 l1 = __floats2bfloat162_rn(v.z - f1.x, v.w - f1.y);
    hi.x = *(unsigned*)&h0; hi.y = *(unsigned*)&h1;
    lo.x = *(unsigned*)&l0; lo.y = *(unsigned*)&l1;
}

__global__ void convX_k(const float4* __restrict__ x)
{
    int i = blockIdx.x * blockDim.x + threadIdx.x;
    uint2 hi, lo;
    split4(x[i], hi, lo);
    ((uint2*)g_xhi)[i] = hi;
    ((uint2*)g_xlo)[i] = lo;
}

__global__ void convW_k(const float4* __restrict__ w0, const float4* __restrict__ w1,
                        const float4* __restrict__ w2, const float4* __restrict__ w3)
{
    const float4* src = (blockIdx.y == 0) ? w0 : (blockIdx.y == 1) ? w1 : (blockIdx.y == 2) ? w2 : w3;
    int i = blockIdx.x * blockDim.x + threadIdx.x;
    uint2 hi, lo;
    split4(src[i], hi, lo);
    size_t off = (size_t)blockIdx.y * (WSEG / 4) + i;
    ((uint2*)g_whi)[off] = hi;
    ((uint2*)g_wlo)[off] = lo;
}

// ---------------------------------------------------------------------------
// Tensor-core GEMM on COMPACT rows (split-bf16, 3-stage cp.async pipeline).
// MODE 0: fused QKV (blockIdx.z selects matrix); A gathered via g_rowsrc,
//         C scattered to (g,h,slot) head-major bf16 hi/lo (Q scaled 0.125).
// MODE 3: A = compact att rows, C = compact g_out fp32.
// ---------------------------------------------------------------------------
#define A_STRIDE 40
#define B_STRIDE 136
#define A_BYTES  (128*A_STRIDE*2)          // 10240
#define B_BYTES  (32*B_STRIDE*2)           // 8704
#define STG_BYTES (2*A_BYTES + 2*B_BYTES)  // 37888
#define SMEM_TOTAL (3*STG_BYTES + 512)     // 114176

template<int MODE>
__global__ __launch_bounds__(256, 2)
void bgemm_k(const float* __restrict__ bias0,
             const float* __restrict__ bias1,
             const float* __restrict__ bias2)
{
    const int Mc = g_Mc;
    const int m0 = blockIdx.y * 128;
    if (m0 >= Mc) return;

    const int z = (MODE == 0) ? blockIdx.z : 3;
    const __nv_bfloat16* Ahi = (MODE == 0) ? g_xhi : g_ahi;
    const __nv_bfloat16* Alo = (MODE == 0) ? g_xlo : g_alo;
    const __nv_bfloat16* Bhi = g_whi + (size_t)z * WSEG;
    const __nv_bfloat16* Blo = g_wlo + (size_t)z * WSEG;
    __nv_bfloat16* Chi = (z == 0) ? g_qhi : (z == 1) ? g_khi : g_vhi;
    __nv_bfloat16* Clo = (z == 0) ? g_qlo : (z == 1) ? g_klo : g_vlo;
    const float* bias = (MODE != 0) ? bias0 : (z == 0) ? bias0 : (z == 1) ? bias1 : bias2;
    const float scl = (MODE == 0 && z == 0) ? 0.125f : 1.f;

    extern __shared__ char smem[];
    const uint32_t sbase = (uint32_t)__cvta_generic_to_shared(smem);
    int* srcrow = (int*)(smem + 3 * STG_BYTES);

    const int tid = threadIdx.x;
    const int lane = tid & 31;
    const int wid = tid >> 5;
    const int wm = wid & 3;
    const int wn = wid >> 2;
    const int n0 = blockIdx.x * 128;

    if (MODE == 0) {
        if (tid < 128) srcrow[tid] = g_rowsrc[m0 + tid];
        __syncthreads();
    }

    float acc[2][8][4];
    #pragma unroll
    for (int a = 0; a < 2; a++)
        #pragma unroll
        for (int b = 0; b < 8; b++)
            #pragma unroll
            for (int c = 0; c < 4; c++) acc[a][b][c] = 0.f;

    const int aid0 = tid * 2;
    #define COPY_STAGE(I, S)                                                        \
    {                                                                               \
        const int k0 = (I) * 32;                                                    \
        const uint32_t sb = sbase + (S) * STG_BYTES;                                \
        _Pragma("unroll")                                                           \
        for (int c = 0; c < 2; c++) {                                               \
            int id = aid0 + c;                                                      \
            int ar = id >> 2, ac = id & 3;                                          \
            size_t arow = (MODE == 0) ? (size_t)srcrow[ar] : (size_t)(m0 + ar);     \
            const __nv_bfloat16* gA = Ahi + arow * Dsz + k0 + ac * 8;               \
            const __nv_bfloat16* gAl = Alo + arow * Dsz + k0 + ac * 8;              \
            uint32_t dA = sb + ar * (A_STRIDE*2) + ac * 16;                         \
            cp16(dA, gA);                                                           \
            cp16(dA + A_BYTES, gAl);                                                \
            int br = id >> 4, bc = id & 15;                                         \
            const __nv_bfloat16* gB = Bhi + (size_t)(k0 + br) * Dsz + n0 + bc * 8;  \
            const __nv_bfloat16* gBl = Blo + (size_t)(k0 + br) * Dsz + n0 + bc * 8; \
            uint32_t dB = sb + 2*A_BYTES + br * (B_STRIDE*2) + bc * 16;             \
            cp16(dB, gB);                                                           \
            cp16(dB + B_BYTES, gBl);                                                \
        }                                                                           \
        asm volatile("cp.async.commit_group;");                                     \
    }

    COPY_STAGE(0, 0);
    COPY_STAGE(1, 1);

    for (int i = 0; i < 16; i++) {
        const int s = i % 3;
        if (i < 15) asm volatile("cp.async.wait_group 1;");
        else        asm volatile("cp.async.wait_group 0;");
        __syncthreads();

        const uint32_t sb   = sbase + s * STG_BYTES;
        const uint32_t sAhi = sb;
        const uint32_t sAlo = sb + A_BYTES;
        const uint32_t sBhi = sb + 2 * A_BYTES;
        const uint32_t sBlo = sBhi + B_BYTES;

        #pragma unroll
        for (int kk = 0; kk < 32; kk += 16) {
            unsigned ah[2][4], al[2][4];
            #pragma unroll
            for (int mt = 0; mt < 2; mt++) {
                uint32_t off = (uint32_t)(wm * 32 + mt * 16 + (lane & 15)) * (A_STRIDE*2)
                             + (kk + (lane >> 4) * 8) * 2;
                ldsm4(ah[mt], sAhi + off);
                ldsm4(al[mt], sAlo + off);
            }
            #pragma unroll
            for (int nn = 0; nn < 64; nn += 16) {
                unsigned bh[4], bl[4];
                uint32_t boff = (uint32_t)(kk + (lane & 15)) * (B_STRIDE*2)
                              + (wn * 64 + nn + (lane >> 4) * 8) * 2;
                ldsm4t(bh, sBhi + boff);
                ldsm4t(bl, sBlo + boff);
                #pragma unroll
                for (int mt = 0; mt < 2; mt++) {
                    #pragma unroll
                    for (int t = 0; t < 2; t++) {
                        mma_bf16(acc[mt][nn/8 + t], ah[mt], bh[2*t], bh[2*t+1]);
                        mma_bf16(acc[mt][nn/8 + t], al[mt], bh[2*t], bh[2*t+1]);
                        mma_bf16(acc[mt][nn/8 + t], ah[mt], bl[2*t], bl[2*t+1]);
                    }
                }
            }
        }
        if (i + 2 < 16) { COPY_STAGE(i + 2, (i + 2) % 3); }
    }

    // epilogue
    #pragma unroll
    for (int mt = 0; mt < 2; mt++) {
        #pragma unroll
        for (int half = 0; half < 2; half++) {
            int m = m0 + wm * 32 + mt * 16 + (lane >> 2) + half * 8;
            if (m >= Mc) continue;
            int bos = (MODE == 0) ? g_rowbos[m] : 0;
            int gg = bos >> 8, sl = bos & 255;
            #pragma unroll
            for (int nt = 0; nt < 8; nt++) {
                int n = n0 + wn * 64 + nt * 8 + (lane & 3) * 2;
                float2 v;
                v.x = acc[mt][nt][half*2 + 0] + bias[n];
                v.y = acc[mt][nt][half*2 + 1] + bias[n + 1];
                if (MODE == 0) {
                    v.x *= scl; v.y *= scl;
                    unsigned hv = packbf(v.x, v.y);
                    float2 hb = __bfloat1622float2(*(__nv_bfloat162*)&hv);
                    unsigned lv = packbf(v.x - hb.x, v.y - hb.y);
                    int h = n >> 6, hd = n & 63;
                    size_t idx = (((size_t)(gg * Hsz + h) * Tsz + sl) * HDsz) + hd;
                    *(unsigned*)&Chi[idx] = hv;
                    *(unsigned*)&Clo[idx] = lv;
                } else {
                    *(float2*)&g_out[(size_t)m * Dsz + n] = v;
                }
            }
        }
    }
    #undef COPY_STAGE
}

// ---------------------------------------------------------------------------
// Tensor-core flash attention on compact slots. 1 CTA per (g,h), 8 warps.
// ---------------------------------------------------------------------------
#define QSTR 144
#define AQHI 0
#define AQLO (256*QSTR)
#define AKHI (2*256*QSTR)
#define AKLO (AKHI + 64*QSTR)
#define AVHI (AKLO + 64*QSTR)
#define AVLO (AVHI + 64*QSTR)
#define ATT_SMEM (AVLO + 64*QSTR)

__global__ __launch_bounds__(256, 1)
void attn_k()
{
    extern __shared__ char sm[];
    const uint32_t sb = (uint32_t)__cvta_generic_to_shared(sm);

    const int blk = blockIdx.x;            // g*8 + h
    const int g = blk >> 3;
    const int h = blk & 7;
    const int nv = g_cnt[g];
    if (nv == 0) return;
    const int gstart = g_gstart[g];
    const int nkb = (nv + 63) >> 6;

    const int tid = threadIdx.x;
    const int lane = tid & 31;
    const int w = tid >> 5;
    const int c0 = (lane & 3) * 2;
    const bool wvalid = (w * 32 < nv);

    const size_t base = (size_t)blk * Tsz * HDsz;

    #pragma unroll
    for (int i = 0; i < 8; i++) {
        int id = tid + i * 256;
        int r = id >> 3, c = id & 7;
        cp16(sb + AQHI + r * QSTR + c * 16, g_qhi + base + (size_t)r * 64 + c * 8);
        cp16(sb + AQLO + r * QSTR + c * 16, g_qlo + base + (size_t)r * 64 + c * 8);
    }
    asm volatile("cp.async.commit_group;");

    float O[2][8][4];
    #pragma unroll
    for (int a = 0; a < 2; a++)
        #pragma unroll
        for (int n = 0; n < 8; n++)
            #pragma unroll
            for (int c = 0; c < 4; c++) O[a][n][c] = 0.f;
    float mrow[2][2] = {{-1e30f, -1e30f}, {-1e30f, -1e30f}};
    float lrow[2][2] = {{0.f, 0.f}, {0.f, 0.f}};

    for (int kb = 0; kb < nkb; kb++) {
        __syncthreads();
        #pragma unroll
        for (int i = 0; i < 2; i++) {
            int id = tid + i * 256;
            int r = id >> 3, c = id & 7;
            int slot = kb * 64 + r;
            uint32_t d = r * QSTR + c * 16;
            if (slot < nv) {
                size_t gb = base + (size_t)slot * 64 + c * 8;
                cp16(sb + AKHI + d, g_khi + gb);
                cp16(sb + AKLO + d, g_klo + gb);
                cp16(sb + AVHI + d, g_vhi + gb);
                cp16(sb + AVLO + d, g_vlo + gb);
            } else {
                st16z(sb + AKHI + d);
                st16z(sb + AKLO + d);
                st16z(sb + AVHI + d);
                st16z(sb + AVLO + d);
            }
        }
        asm volatile("cp.async.commit_group;");
        asm volatile("cp.async.wait_group 0;");
        __syncthreads();

        if (!wvalid) continue;   // no barriers below within this iteration

        float s[2][8][4];
        #pragma unroll
        for (int a = 0; a < 2; a++)
            #pragma unroll
            for (int n = 0; n < 8; n++)
                #pragma unroll
                for (int c = 0; c < 4; c++) s[a][n][c] = 0.f;

        #pragma unroll
        for (int kk = 0; kk < 64; kk += 16) {
            unsigned ah[2][4], al[2][4];
            #pragma unroll
            for (int mt = 0; mt < 2; mt++) {
                uint32_t aoff = (uint32_t)(w * 32 + mt * 16 + (lane & 15)) * QSTR
                              + (kk + (lane >> 4) * 8) * 2;
                ldsm4(ah[mt], sb + AQHI + aoff);
                ldsm4(al[mt], sb + AQLO + aoff);
            }
            #pragma unroll
            for (int nn = 0; nn < 64; nn += 16) {
                int row = nn + ((lane >> 4) << 3) + (lane & 7);
                int kc  = kk + (((lane >> 3) & 1) << 3);
                uint32_t boff = (uint32_t)row * QSTR + kc * 2;
                unsigned bh[4], bl[4];
                ldsm4(bh, sb + AKHI + boff);
                ldsm4(bl, sb + AKLO + boff);
                #pragma unroll
                for (int mt = 0; mt < 2; mt++) {
                    #pragma unroll
                    for (int t = 0; t < 2; t++) {
                        mma_bf16(s[mt][nn/8 + t], ah[mt], bh[2*t], bh[2*t+1]);
                        mma_bf16(s[mt][nn/8 + t], al[mt], bh[2*t], bh[2*t+1]);
                        mma_bf16(s[mt][nn/8 + t], ah[mt], bl[2*t], bl[2*t+1]);
                    }
                }
            }
        }

        // padded-slot bias + online softmax
        float nm[2][2] = {{mrow[0][0], mrow[0][1]}, {mrow[1][0], mrow[1][1]}};
        #pragma unroll
        for (int n8 = 0; n8 < 8; n8++) {
            int slot0 = kb * 64 + n8 * 8 + c0;
            float b0 = (slot0     < nv) ? 0.f : -1e30f;
            float b1 = (slot0 + 1 < nv) ? 0.f : -1e30f;
            #pragma unroll
            for (int mt = 0; mt < 2; mt++) {
                s[mt][n8][0] += b0; s[mt][n8][1] += b1;
                s[mt][n8][2] += b0; s[mt][n8][3] += b1;
                nm[mt][0] = fmaxf(nm[mt][0], fmaxf(s[mt][n8][0], s[mt][n8][1]));
                nm[mt][1] = fmaxf(nm[mt][1], fmaxf(s[mt][n8][2], s[mt][n8][3]));
            }
        }
        #pragma unroll
        for (int mt = 0; mt < 2; mt++)
            #pragma unroll
            for (int hf = 0; hf < 2; hf++) {
                float v = nm[mt][hf];
                v = fmaxf(v, __shfl_xor_sync(0xffffffffu, v, 1));
                v = fmaxf(v, __shfl_xor_sync(0xffffffffu, v, 2));
                nm[mt][hf] = v;
            }

        float rs[2][2] = {{0.f, 0.f}, {0.f, 0.f}};
        #pragma unroll
        for (int mt = 0; mt < 2; mt++)
            #pragma unroll
            for (int n8 = 0; n8 < 8; n8++) {
                float p0 = __expf(s[mt][n8][0] - nm[mt][0]);
                float p1 = __expf(s[mt][n8][1] - nm[mt][0]);
                float p2 = __expf(s[mt][n8][2] - nm[mt][1]);
                float p3 = __expf(s[mt][n8][3] - nm[mt][1]);
                s[mt][n8][0] = p0; s[mt][n8][1] = p1;
                s[mt][n8][2] = p2; s[mt][n8][3] = p3;
                rs[mt][0] += p0 + p1;
                rs[mt][1] += p2 + p3;
            }
        float alpha[2][2];
        #pragma unroll
        for (int mt = 0; mt < 2; mt++)
            #pragma unroll
            for (int hf = 0; hf < 2; hf++) {
                float v = rs[mt][hf];
                v += __shfl_xor_sync(0xffffffffu, v, 1);
                v += __shfl_xor_sync(0xffffffffu, v, 2);
                float al = __expf(mrow[mt][hf] - nm[mt][hf]);
                lrow[mt][hf] = lrow[mt][hf] * al + v;
                mrow[mt][hf] = nm[mt][hf];
                alpha[mt][hf] = al;
            }
        #pragma unroll
        for (int mt = 0; mt < 2; mt++)
            #pragma unroll
            for (int n8 = 0; n8 < 8; n8++) {
                O[mt][n8][0] *= alpha[mt][0]; O[mt][n8][1] *= alpha[mt][0];
                O[mt][n8][2] *= alpha[mt][1]; O[mt][n8][3] *= alpha[mt][1];
            }

        #pragma unroll
        for (int j = 0; j < 4; j++) {
            unsigned pa_hi[2][4], pa_lo[2][4];
            #pragma unroll
            for (int mt = 0; mt < 2; mt++) {
                #pragma unroll
                for (int q = 0; q < 2; q++) {
                    float p0 = s[mt][2*j + q][0], p1 = s[mt][2*j + q][1];
                    float p2 = s[mt][2*j + q][2], p3 = s[mt][2*j + q][3];
                    unsigned h0 = packbf(p0, p1);
                    unsigned h1 = packbf(p2, p3);
                    float2 f0 = __bfloat1622float2(*(__nv_bfloat162*)&h0);
                    float2 f1 = __bfloat1622float2(*(__nv_bfloat162*)&h1);
                    pa_hi[mt][2*q]   = h0;
                    pa_hi[mt][2*q+1] = h1;
                    pa_lo[mt][2*q]   = packbf(p0 - f0.x, p1 - f0.y);
                    pa_lo[mt][2*q+1] = packbf(p2 - f1.x, p3 - f1.y);
                }
            }
            #pragma unroll
            for (int nn = 0; nn < 64; nn += 16) {
                uint32_t boff = (uint32_t)(j * 16 + (lane & 15)) * QSTR
                              + (nn + (lane >> 4) * 8) * 2;
                unsigned vh[4], vl[4];
                ldsm4t(vh, sb + AVHI + boff);
                ldsm4t(vl, sb + AVLO + boff);
                #pragma unroll
                for (int mt = 0; mt < 2; mt++) {
                    #pragma unroll
                    for (int t = 0; t < 2; t++) {
                        mma_bf16(O[mt][nn/8 + t], pa_hi[mt], vh[2*t], vh[2*t+1]);
                        mma_bf16(O[mt][nn/8 + t], pa_lo[mt], vh[2*t], vh[2*t+1]);
                        mma_bf16(O[mt][nn/8 + t], pa_hi[mt], vl[2*t], vl[2*t+1]);
                    }
                }
            }
        }
    }

    if (!wvalid) return;

    float inv[2][2];
    #pragma unroll
    for (int mt = 0; mt < 2; mt++)
        #pragma unroll
        for (int hf = 0; hf < 2; hf++)
            inv[mt][hf] = (mrow[mt][hf] > -1e29f && lrow[mt][hf] > 0.f)
                        ? (1.f / lrow[mt][hf]) : 0.f;

    #pragma unroll
    for (int mt = 0; mt < 2; mt++) {
        #pragma unroll
        for (int hf = 0; hf < 2; hf++) {
            int slot = w * 32 + mt * 16 + (lane >> 2) + hf * 8;
            if (slot >= nv) continue;
            size_t orow = (size_t)(gstart + slot) * Dsz + (size_t)h * 64;
            #pragma unroll
            for (int n8 = 0; n8 < 8; n8++) {
                float v0 = O[mt][n8][hf*2 + 0] * inv[mt][hf];
                float v1 = O[mt][n8][hf*2 + 1] * inv[mt][hf];
                unsigned hv = packbf(v0, v1);
                float2 hb = __bfloat1622float2(*(__nv_bfloat162*)&hv);
                unsigned lv = packbf(v0 - hb.x, v1 - hb.y);
                size_t idx = orow + n8 * 8 + c0;
                *(unsigned*)&g_ahi[idx] = hv;
                *(unsigned*)&g_alo[idx] = lv;
            }
        }
    }
}

// ---------------------------------------------------------------------------
// Zero full output, then LayerNorm on compact rows (gather x, scatter y)
// ---------------------------------------------------------------------------
__global__ void zero_y_k(float4* __restrict__ y)
{
    y[blockIdx.x * blockDim.x + threadIdx.x] = make_float4(0.f, 0.f, 0.f, 0.f);
}

__global__ __launch_bounds__(128)
void ln_k(const float4* __restrict__ x,
          const float4* __restrict__ gamma,
          const float4* __restrict__ beta,
          float4* __restrict__ y)
{
    __shared__ float s1[4], s2[4];
    __shared__ float stats[2];

    const int r = blockIdx.x;
    if (r >= g_Mc) return;
    const int tid = threadIdx.x;
    const int xrow = g_rowsrc[r];

    float4 a = ((const float4*)g_out)[(size_t)r * 128 + tid];
    float4 xr = x[(size_t)xrow * 128 + tid];
    float4 rr;
    rr.x = a.x + xr.x; rr.y = a.y + xr.y; rr.z = a.z + xr.z; rr.w = a.w + xr.w;

    float s = rr.x + rr.y + rr.z + rr.w;
    float ss = rr.x * rr.x + rr.y * rr.y + rr.z * rr.z + rr.w * rr.w;
    #pragma unroll
    for (int off = 16; off > 0; off >>= 1) {
        s  += __shfl_down_sync(0xffffffffu, s, off);
        ss += __shfl_down_sync(0xffffffffu, ss, off);
    }
    if ((tid & 31) == 0) { s1[tid >> 5] = s; s2[tid >> 5] = ss; }
    __syncthreads();
    if (tid == 0) {
        float a2 = 0.f, b2 = 0.f;
        #pragma unroll
        for (int i = 0; i < 4; i++) { a2 += s1[i]; b2 += s2[i]; }
        stats[0] = a2; stats[1] = b2;
    }
    __syncthreads();

    float mean = stats[0] * (1.f / 512.f);
    float var  = stats[1] * (1.f / 512.f) - mean * mean;
    float rstd = rsqrtf(var + 1e-5f);

    float4 g = gamma[tid], bb = beta[tid];
    float4 out;
    out.x = (rr.x - mean) * rstd * g.x + bb.x;
    out.y = (rr.y - mean) * rstd * g.y + bb.y;
    out.z = (rr.z - mean) * rstd * g.z + bb.z;
    out.w = (rr.w - mean) * rstd * g.w + bb.w;
    y[(size_t)xrow * 128 + tid] = out;
}

// ---------------------------------------------------------------------------
// Launch
// ---------------------------------------------------------------------------
extern "C" void kernel_launch(void* const* d_in, const int* in_sizes, int n_in,
                              void* d_out, int out_size)
{
    const float* x   = (const float*)d_in[0];
    const void* mask = d_in[1];
    const float* Wq = (const float*)d_in[2];
    const float* bq = (const float*)d_in[3];
    const float* Wk = (const float*)d_in[4];
    const float* bk = (const float*)d_in[5];
    const float* Wv = (const float*)d_in[6];
    const float* bv = (const float*)d_in[7];
    const float* Wo = (const float*)d_in[8];
    const float* bo = (const float*)d_in[9];
    const float* gamma = (const float*)d_in[10];
    const float* beta  = (const float*)d_in[11];
    float* y = (float*)d_out;

    cudaFuncSetAttribute(bgemm_k<0>, cudaFuncAttributeMaxDynamicSharedMemorySize, SMEM_TOTAL);
    cudaFuncSetAttribute(bgemm_k<3>, cudaFuncAttributeMaxDynamicSharedMemorySize, SMEM_TOTAL);
    cudaFuncSetAttribute(attn_k, cudaFuncAttributeMaxDynamicSharedMemorySize, ATT_SMEM);

    mask_norm_k<<<1, 1024>>>(mask);
    comp_scan_k<<<NGRP, 256>>>();
    gstart_k<<<1, NGRP>>>();
    rowmap_k<<<NGRP, 256>>>();
    convW_k<<<dim3(256, 4), 256>>>((const float4*)Wq, (const float4*)Wk,
                                   (const float4*)Wv, (const float4*)Wo);
    convX_k<<<ELEMS / 4 / 256, 256>>>((const float4*)x);

    dim3 gqkv(Dsz / 128, Mrows / 128, 3);   // (4, 256, 3); CTAs beyond Mc exit
    bgemm_k<0><<<gqkv, 256, SMEM_TOTAL>>>(bq, bk, bv);
    attn_k<<<NGRP * Hsz, 256, ATT_SMEM>>>();
    dim3 go(Dsz / 128, Mrows / 128);
    bgemm_k<3><<<go, 256, SMEM_TOTAL>>>(bo, bo, bo);
    zero_y_k<<<ELEMS / 4 / 256, 256>>>((float4*)y);
    ln_k<<<Mrows, 128>>>((const float4*)x, (const float4*)gamma,
                         (const float4*)beta, (float4*)y);
}